// round 1
// baseline (speedup 1.0000x reference)
#include <cuda_runtime.h>
#include <cuda_bf16.h>
#include <math.h>

// Problem constants
#define BB 4
#define SS 2048
#define DD 1024
#define HH 16
#define DKK 64
#define DFF 4096
#define NTOK (BB*SS)          // 8192
#define EPS 1e-5f

// ---------------- scratch (device globals; no allocation allowed) ----------
__device__ float g_h   [NTOK*DD];    // LN1 output
__device__ float g_q   [NTOK*DD];
__device__ float g_k   [NTOK*DD];
__device__ float g_v   [NTOK*DD];
__device__ float g_attn[NTOK*DD];
__device__ float g_x1  [NTOK*DD];    // after first residual
__device__ float g_h2  [NTOK*DD];    // LN2 output
__device__ float g_ffn [NTOK*DFF];   // relu(h2@w1+b1)

// ---------------- LayerNorm: one block per row of 1024 ---------------------
__global__ void ln_kernel(const float* __restrict__ x, const float* __restrict__ g,
                          const float* __restrict__ b, float* __restrict__ out) {
    int row = blockIdx.x;
    int tid = threadIdx.x;                       // 256 threads
    const float4* xr = (const float4*)(x + (size_t)row * DD);
    float4 v = xr[tid];
    float s  = v.x + v.y + v.z + v.w;
    float s2 = v.x*v.x + v.y*v.y + v.z*v.z + v.w*v.w;

    // block reduce (sum, sumsq)
    #pragma unroll
    for (int o = 16; o > 0; o >>= 1) {
        s  += __shfl_down_sync(0xffffffffu, s,  o);
        s2 += __shfl_down_sync(0xffffffffu, s2, o);
    }
    __shared__ float sa[8], sb[8];
    int w = tid >> 5, l = tid & 31;
    if (l == 0) { sa[w] = s; sb[w] = s2; }
    __syncthreads();
    if (w == 0) {
        s  = (l < 8) ? sa[l] : 0.f;
        s2 = (l < 8) ? sb[l] : 0.f;
        #pragma unroll
        for (int o = 4; o > 0; o >>= 1) {
            s  += __shfl_down_sync(0xffffffffu, s,  o);
            s2 += __shfl_down_sync(0xffffffffu, s2, o);
        }
        if (l == 0) { sa[0] = s; sb[0] = s2; }
    }
    __syncthreads();
    float mean = sa[0] * (1.0f / DD);
    float var  = sb[0] * (1.0f / DD) - mean * mean;
    float inv  = rsqrtf(var + EPS);

    float4 gg = ((const float4*)g)[tid];
    float4 bb = ((const float4*)b)[tid];
    float4 o4;
    o4.x = (v.x - mean) * inv * gg.x + bb.x;
    o4.y = (v.y - mean) * inv * gg.y + bb.y;
    o4.z = (v.z - mean) * inv * gg.z + bb.z;
    o4.w = (v.w - mean) * inv * gg.w + bb.w;
    ((float4*)(out + (size_t)row * DD))[tid] = o4;
}

// ---------------- SGEMM: C[M,N] = A[M,K] @ B[K,N], fused epilogues ---------
// EPI: 0 = none, 1 = relu(C+bias), 2 = C+res, 3 = C+bias+res
template<int EPI>
__global__ void __launch_bounds__(256)
sgemm128(const float* __restrict__ A, const float* __restrict__ B,
         const float* __restrict__ bias, const float* __restrict__ res,
         float* __restrict__ C, int M, int N, int K) {
    __shared__ float As[8][128];   // transposed A tile (k-major)
    __shared__ float Bs[8][128];

    int tid = threadIdx.x;                 // 0..255
    int tx = tid & 15, ty = tid >> 4;      // 16x16
    int rowBase = blockIdx.y * 128;
    int colBase = blockIdx.x * 128;

    int aRow = tid >> 1;                   // 0..127
    int aCol = (tid & 1) * 4;              // 0 or 4
    int bRow = tid >> 5;                   // 0..7
    int bCol = (tid & 31) * 4;

    const float* Aptr = A + (size_t)(rowBase + aRow) * K + aCol;
    const float* Bptr = B + (size_t)bRow * N + colBase + bCol;

    float acc[8][8];
    #pragma unroll
    for (int i = 0; i < 8; i++)
        #pragma unroll
        for (int j = 0; j < 8; j++) acc[i][j] = 0.f;

    for (int k0 = 0; k0 < K; k0 += 8) {
        float4 a4 = *(const float4*)Aptr;  Aptr += 8;
        float4 b4 = *(const float4*)Bptr;  Bptr += (size_t)8 * N;

        As[aCol + 0][aRow] = a4.x;
        As[aCol + 1][aRow] = a4.y;
        As[aCol + 2][aRow] = a4.z;
        As[aCol + 3][aRow] = a4.w;
        *(float4*)&Bs[bRow][bCol] = b4;
        __syncthreads();

        #pragma unroll
        for (int kk = 0; kk < 8; kk++) {
            float ra[8], rb[8];
            #pragma unroll
            for (int i = 0; i < 8; i++) ra[i] = As[kk][ty * 8 + i];
            #pragma unroll
            for (int j = 0; j < 8; j++) rb[j] = Bs[kk][tx * 8 + j];
            #pragma unroll
            for (int i = 0; i < 8; i++)
                #pragma unroll
                for (int j = 0; j < 8; j++)
                    acc[i][j] = fmaf(ra[i], rb[j], acc[i][j]);
        }
        __syncthreads();
    }

    // epilogue
    float bv[8];
    if (EPI == 1 || EPI == 3) {
        #pragma unroll
        for (int j = 0; j < 8; j++) bv[j] = bias[colBase + tx * 8 + j];
    }
    #pragma unroll
    for (int i = 0; i < 8; i++) {
        size_t r = (size_t)(rowBase + ty * 8 + i);
        float* cp = C + r * N + colBase + tx * 8;
        const float* rp = (EPI >= 2) ? (res + r * N + colBase + tx * 8) : nullptr;
        #pragma unroll
        for (int j = 0; j < 8; j += 4) {
            float4 o;
            float v0 = acc[i][j+0], v1 = acc[i][j+1], v2 = acc[i][j+2], v3 = acc[i][j+3];
            if (EPI == 1) {
                v0 = fmaxf(v0 + bv[j+0], 0.f); v1 = fmaxf(v1 + bv[j+1], 0.f);
                v2 = fmaxf(v2 + bv[j+2], 0.f); v3 = fmaxf(v3 + bv[j+3], 0.f);
            } else if (EPI == 2) {
                v0 += rp[j+0]; v1 += rp[j+1]; v2 += rp[j+2]; v3 += rp[j+3];
            } else if (EPI == 3) {
                v0 += bv[j+0] + rp[j+0]; v1 += bv[j+1] + rp[j+1];
                v2 += bv[j+2] + rp[j+2]; v3 += bv[j+3] + rp[j+3];
            }
            o.x = v0; o.y = v1; o.z = v2; o.w = v3;
            *(float4*)(cp + j) = o;
        }
    }
}

// ---------------- Flash attention: BM=BN=64, DK=64 -------------------------
// q,k,v are [B,S,D] with head h at column offset h*64. Output same layout.
#define FA_PAD 68
__global__ void __launch_bounds__(256)
flash_attn(const float* __restrict__ Q, const float* __restrict__ K,
           const float* __restrict__ V, float* __restrict__ O) {
    extern __shared__ float sm[];
    float* Qst = sm;                       // [d][i] : 64 x FA_PAD
    float* Kst = Qst + 64 * FA_PAD;        // [d][j]
    float* Vs  = Kst + 64 * FA_PAD;        // [j][d]
    float* Sb  = Vs  + 64 * FA_PAD;        // [i][j] (reused for P)
    __shared__ float m_s[64], l_s[64], alpha_s[64];

    int tid = threadIdx.x;
    int tx = tid & 15, ty = tid >> 4;      // 16x16, 4x4 microtile
    int qt = blockIdx.x;                   // query tile 0..31
    int bh = blockIdx.y;                   // 0..63
    int b = bh >> 4, h = bh & 15;
    size_t base = (size_t)b * SS * DD + (size_t)h * DKK;   // + s*DD

    // load Q tile (scaled by 1/sqrt(64)=0.125), transposed to d-major
    for (int t = tid; t < 64 * 16; t += 256) {
        int r  = t >> 4;
        int c4 = (t & 15) * 4;
        float4 q4 = *(const float4*)(Q + base + (size_t)(qt * 64 + r) * DD + c4);
        Qst[(c4 + 0) * FA_PAD + r] = q4.x * 0.125f;
        Qst[(c4 + 1) * FA_PAD + r] = q4.y * 0.125f;
        Qst[(c4 + 2) * FA_PAD + r] = q4.z * 0.125f;
        Qst[(c4 + 3) * FA_PAD + r] = q4.w * 0.125f;
    }
    if (tid < 64) { m_s[tid] = -1e30f; l_s[tid] = 0.f; }

    float acc[4][4];
    #pragma unroll
    for (int i = 0; i < 4; i++)
        #pragma unroll
        for (int j = 0; j < 4; j++) acc[i][j] = 0.f;

    for (int kt = 0; kt < SS / 64; kt++) {
        __syncthreads();   // also covers initial Q-load visibility
        // load K (transposed) and V tiles
        for (int t = tid; t < 64 * 16; t += 256) {
            int r  = t >> 4;
            int c4 = (t & 15) * 4;
            size_t gro = base + (size_t)(kt * 64 + r) * DD + c4;
            float4 k4 = *(const float4*)(K + gro);
            Kst[(c4 + 0) * FA_PAD + r] = k4.x;
            Kst[(c4 + 1) * FA_PAD + r] = k4.y;
            Kst[(c4 + 2) * FA_PAD + r] = k4.z;
            Kst[(c4 + 3) * FA_PAD + r] = k4.w;
            float4 v4 = *(const float4*)(V + gro);
            *(float4*)&Vs[r * FA_PAD + c4] = v4;
        }
        __syncthreads();

        // S = Q @ K^T (scaled)
        float s[4][4];
        #pragma unroll
        for (int i = 0; i < 4; i++)
            #pragma unroll
            for (int j = 0; j < 4; j++) s[i][j] = 0.f;
        for (int d = 0; d < 64; d++) {
            float ra[4], rb[4];
            #pragma unroll
            for (int i = 0; i < 4; i++) ra[i] = Qst[d * FA_PAD + ty * 4 + i];
            #pragma unroll
            for (int j = 0; j < 4; j++) rb[j] = Kst[d * FA_PAD + tx * 4 + j];
            #pragma unroll
            for (int i = 0; i < 4; i++)
                #pragma unroll
                for (int j = 0; j < 4; j++)
                    s[i][j] = fmaf(ra[i], rb[j], s[i][j]);
        }
        #pragma unroll
        for (int i = 0; i < 4; i++)
            #pragma unroll
            for (int j = 0; j < 4; j++)
                Sb[(ty * 4 + i) * FA_PAD + tx * 4 + j] = s[i][j];
        __syncthreads();

        // online softmax: 4 threads per row
        {
            int row = tid >> 2;
            int qtr = tid & 3;
            float mx = -1e30f;
            #pragma unroll
            for (int j = 0; j < 16; j++)
                mx = fmaxf(mx, Sb[row * FA_PAD + qtr * 16 + j]);
            mx = fmaxf(mx, __shfl_xor_sync(0xffffffffu, mx, 1));
            mx = fmaxf(mx, __shfl_xor_sync(0xffffffffu, mx, 2));
            float m_old = m_s[row];
            float m_new = fmaxf(m_old, mx);
            float sum = 0.f;
            #pragma unroll
            for (int j = 0; j < 16; j++) {
                float p = __expf(Sb[row * FA_PAD + qtr * 16 + j] - m_new);
                Sb[row * FA_PAD + qtr * 16 + j] = p;
                sum += p;
            }
            sum += __shfl_xor_sync(0xffffffffu, sum, 1);
            sum += __shfl_xor_sync(0xffffffffu, sum, 2);
            if (qtr == 0) {
                float al = __expf(m_old - m_new);
                alpha_s[row] = al;
                l_s[row] = l_s[row] * al + sum;
                m_s[row] = m_new;
            }
        }
        __syncthreads();

        // rescale accumulator, then acc += P @ V
        float al[4];
        #pragma unroll
        for (int i = 0; i < 4; i++) al[i] = alpha_s[ty * 4 + i];
        #pragma unroll
        for (int i = 0; i < 4; i++)
            #pragma unroll
            for (int j = 0; j < 4; j++) acc[i][j] *= al[i];

        for (int jj = 0; jj < 64; jj++) {
            float rp[4], rv[4];
            #pragma unroll
            for (int i = 0; i < 4; i++) rp[i] = Sb[(ty * 4 + i) * FA_PAD + jj];
            #pragma unroll
            for (int j = 0; j < 4; j++) rv[j] = Vs[jj * FA_PAD + tx * 4 + j];
            #pragma unroll
            for (int i = 0; i < 4; i++)
                #pragma unroll
                for (int j = 0; j < 4; j++)
                    acc[i][j] = fmaf(rp[i], rv[j], acc[i][j]);
        }
    }

    // final normalize & write back to [B,S,D]
    #pragma unroll
    for (int i = 0; i < 4; i++) {
        float inv = 1.f / l_s[ty * 4 + i];
        float4 o;
        o.x = acc[i][0] * inv; o.y = acc[i][1] * inv;
        o.z = acc[i][2] * inv; o.w = acc[i][3] * inv;
        size_t srow = (size_t)(b * SS + qt * 64 + ty * 4 + i);
        *(float4*)(O + srow * DD + h * DKK + tx * 4) = o;
    }
}

// ---------------- launch --------------------------------------------------
extern "C" void kernel_launch(void* const* d_in, const int* in_sizes, int n_in,
                              void* d_out, int out_size) {
    (void)in_sizes; (void)n_in; (void)out_size;
    const float* x   = (const float*)d_in[0];
    const float* wq  = (const float*)d_in[1];
    const float* wk  = (const float*)d_in[2];
    const float* wv  = (const float*)d_in[3];
    const float* wo  = (const float*)d_in[4];
    const float* w1  = (const float*)d_in[5];
    const float* b1  = (const float*)d_in[6];
    const float* w2  = (const float*)d_in[7];
    const float* b2  = (const float*)d_in[8];
    const float* g1  = (const float*)d_in[9];
    const float* be1 = (const float*)d_in[10];
    const float* g2  = (const float*)d_in[11];
    const float* be2 = (const float*)d_in[12];
    float* out = (float*)d_out;

    float *h, *q, *k, *v, *attn, *x1, *h2, *ffn;
    cudaGetSymbolAddress((void**)&h,    g_h);
    cudaGetSymbolAddress((void**)&q,    g_q);
    cudaGetSymbolAddress((void**)&k,    g_k);
    cudaGetSymbolAddress((void**)&v,    g_v);
    cudaGetSymbolAddress((void**)&attn, g_attn);
    cudaGetSymbolAddress((void**)&x1,   g_x1);
    cudaGetSymbolAddress((void**)&h2,   g_h2);
    cudaGetSymbolAddress((void**)&ffn,  g_ffn);

    const size_t ATT_SMEM = 4 * 64 * FA_PAD * sizeof(float);
    cudaFuncSetAttribute(flash_attn, cudaFuncAttributeMaxDynamicSharedMemorySize,
                         (int)ATT_SMEM);

    // 1) LN1
    ln_kernel<<<NTOK, 256>>>(x, g1, be1, h);
    // 2) QKV projections
    sgemm128<0><<<dim3(DD/128, NTOK/128), 256>>>(h, wq, nullptr, nullptr, q, NTOK, DD, DD);
    sgemm128<0><<<dim3(DD/128, NTOK/128), 256>>>(h, wk, nullptr, nullptr, k, NTOK, DD, DD);
    sgemm128<0><<<dim3(DD/128, NTOK/128), 256>>>(h, wv, nullptr, nullptr, v, NTOK, DD, DD);
    // 3) attention
    flash_attn<<<dim3(SS/64, BB*HH), 256, ATT_SMEM>>>(q, k, v, attn);
    // 4) x1 = x + attn @ wo
    sgemm128<2><<<dim3(DD/128, NTOK/128), 256>>>(attn, wo, nullptr, x, x1, NTOK, DD, DD);
    // 5) LN2
    ln_kernel<<<NTOK, 256>>>(x1, g2, be2, h2);
    // 6) ffn = relu(h2 @ w1 + b1)
    sgemm128<1><<<dim3(DFF/128, NTOK/128), 256>>>(h2, w1, b1, nullptr, ffn, NTOK, DFF, DD);
    // 7) out = x1 + ffn @ w2 + b2
    sgemm128<3><<<dim3(DD/128, NTOK/128), 256>>>(ffn, w2, b2, x1, out, NTOK, DD, DFF);
}

// round 3
// speedup vs baseline: 3.2714x; 3.2714x over previous
#include <cuda_runtime.h>
#include <cstdint>
#include <math.h>

// Problem constants
#define BBATCH 4
#define SS 2048
#define DD 1024
#define HH 16
#define DKK 64
#define DFFN 4096
#define NTOK (BBATCH*SS)          // 8192
#define EPS 1e-5f

// ---------------- scratch (device globals) ---------------------------------
__device__ float g_h   [NTOK*DD];
__device__ float g_q   [NTOK*DD];
__device__ float g_k   [NTOK*DD];
__device__ float g_v   [NTOK*DD];
__device__ float g_attn[NTOK*DD];
__device__ float g_x1  [NTOK*DD];
__device__ float g_h2  [NTOK*DD];
__device__ float g_ffn [NTOK*DFFN];

// ---------------- PTX helpers ----------------------------------------------
__device__ __forceinline__ void cp_async16(unsigned int saddr, const void* gptr) {
    asm volatile("cp.async.ca.shared.global [%0], [%1], 16;\n" :: "r"(saddr), "l"(gptr));
}
__device__ __forceinline__ void cp_commit() { asm volatile("cp.async.commit_group;\n"); }
__device__ __forceinline__ void cp_wait0()  { asm volatile("cp.async.wait_group 0;\n"); }

__device__ __forceinline__ void mma_tf32(float& c0, float& c1, float& c2, float& c3,
                                         unsigned int a0, unsigned int a1,
                                         unsigned int a2, unsigned int a3,
                                         unsigned int b0, unsigned int b1) {
    asm volatile("mma.sync.aligned.m16n8k8.row.col.f32.tf32.tf32.f32 "
                 "{%0,%1,%2,%3},{%4,%5,%6,%7},{%8,%9},{%0,%1,%2,%3};\n"
                 : "+f"(c0), "+f"(c1), "+f"(c2), "+f"(c3)
                 : "r"(a0), "r"(a1), "r"(a2), "r"(a3), "r"(b0), "r"(b1));
}
__device__ __forceinline__ unsigned int fasu(float x) { return __float_as_uint(x); }

// ---------------- LayerNorm -------------------------------------------------
__global__ void ln_kernel(const float* __restrict__ x, const float* __restrict__ g,
                          const float* __restrict__ b, float* __restrict__ out) {
    int row = blockIdx.x;
    int tid = threadIdx.x;                       // 256 threads
    const float4* xr = (const float4*)(x + (size_t)row * DD);
    float4 v = xr[tid];
    float s  = v.x + v.y + v.z + v.w;
    float s2 = v.x*v.x + v.y*v.y + v.z*v.z + v.w*v.w;
    #pragma unroll
    for (int o = 16; o > 0; o >>= 1) {
        s  += __shfl_down_sync(0xffffffffu, s,  o);
        s2 += __shfl_down_sync(0xffffffffu, s2, o);
    }
    __shared__ float sa[8], sb[8];
    int w = tid >> 5, l = tid & 31;
    if (l == 0) { sa[w] = s; sb[w] = s2; }
    __syncthreads();
    if (w == 0) {
        s  = (l < 8) ? sa[l] : 0.f;
        s2 = (l < 8) ? sb[l] : 0.f;
        #pragma unroll
        for (int o = 4; o > 0; o >>= 1) {
            s  += __shfl_down_sync(0xffffffffu, s,  o);
            s2 += __shfl_down_sync(0xffffffffu, s2, o);
        }
        if (l == 0) { sa[0] = s; sb[0] = s2; }
    }
    __syncthreads();
    float mean = sa[0] * (1.0f / DD);
    float var  = sb[0] * (1.0f / DD) - mean * mean;
    float inv  = rsqrtf(var + EPS);
    float4 gg = ((const float4*)g)[tid];
    float4 bb = ((const float4*)b)[tid];
    float4 o4;
    o4.x = (v.x - mean) * inv * gg.x + bb.x;
    o4.y = (v.y - mean) * inv * gg.y + bb.y;
    o4.z = (v.z - mean) * inv * gg.z + bb.z;
    o4.w = (v.w - mean) * inv * gg.w + bb.w;
    ((float4*)(out + (size_t)row * DD))[tid] = o4;
}

// ---------------- TF32 tensor-core GEMM ------------------------------------
// C[M,N] = A[M,K](row) @ B[K,N](row), fused epilogue.
// Block tile 128x128, K-step 32, 8 warps (warp tile 32x64), double-buffered cp.async.
#define AS_STRIDE 36
#define BS_STRIDE 132
#define AS_SIZE (128*AS_STRIDE)
#define BS_SIZE (32*BS_STRIDE)
#define GEMM_SMEM ((2*AS_SIZE + 2*BS_SIZE)*4)

template<int EPI>  // 0=none, 1=relu(C+bias), 2=C+res, 3=C+bias+res
__global__ void __launch_bounds__(256)
tgemm(const float* __restrict__ A, const float* __restrict__ B,
      const float* __restrict__ bias, const float* __restrict__ res,
      float* __restrict__ C, int M, int N, int K) {
    extern __shared__ float smx[];
    float* As0 = smx;
    float* As1 = smx + AS_SIZE;
    float* Bs0 = smx + 2*AS_SIZE;
    float* Bs1 = smx + 2*AS_SIZE + BS_SIZE;

    int tid = threadIdx.x, lane = tid & 31, warp = tid >> 5;
    int g = lane >> 2, qd = lane & 3;
    int wm = warp >> 1, wn = warp & 1;
    int rowBase = blockIdx.y * 128, colBase = blockIdx.x * 128;

    float acc[2][8][4];
    #pragma unroll
    for (int mt = 0; mt < 2; mt++)
        #pragma unroll
        for (int nt = 0; nt < 8; nt++)
            #pragma unroll
            for (int e = 0; e < 4; e++) acc[mt][nt][e] = 0.f;

    #define LOAD_A(dst, k0)                                                     \
        { _Pragma("unroll")                                                     \
          for (int i = 0; i < 4; i++) {                                         \
              int c = tid + 256*i;                                              \
              int r = c >> 3, kc = (c & 7) * 4;                                 \
              unsigned int s = (unsigned int)__cvta_generic_to_shared(&(dst)[r*AS_STRIDE + kc]); \
              cp_async16(s, A + (size_t)(rowBase + r) * K + (k0) + kc);         \
          } }
    #define LOAD_B(dst, k0)                                                     \
        { _Pragma("unroll")                                                     \
          for (int i = 0; i < 4; i++) {                                         \
              int c = tid + 256*i;                                              \
              int r = c >> 5, nc = (c & 31) * 4;                                \
              unsigned int s = (unsigned int)__cvta_generic_to_shared(&(dst)[r*BS_STRIDE + nc]); \
              cp_async16(s, B + (size_t)((k0) + r) * N + colBase + nc);         \
          } }

    LOAD_A(As0, 0); LOAD_B(Bs0, 0); cp_commit();
    int nk = K / 32;
    for (int kt = 0; kt < nk; kt++) {
        cp_wait0();
        __syncthreads();
        const float* a_s = (kt & 1) ? As1 : As0;
        const float* b_s = (kt & 1) ? Bs1 : Bs0;
        if (kt + 1 < nk) {
            float* an = (kt & 1) ? As0 : As1;
            float* bn = (kt & 1) ? Bs0 : Bs1;
            LOAD_A(an, (kt + 1) * 32); LOAD_B(bn, (kt + 1) * 32); cp_commit();
        }
        #pragma unroll
        for (int ks = 0; ks < 4; ks++) {
            unsigned int af[2][4], bf[8][2];
            #pragma unroll
            for (int mt = 0; mt < 2; mt++) {
                int r0 = wm*32 + mt*16 + g;
                int c0 = ks*8 + qd;
                af[mt][0] = fasu(a_s[ r0   *AS_STRIDE + c0    ]);
                af[mt][1] = fasu(a_s[(r0+8)*AS_STRIDE + c0    ]);
                af[mt][2] = fasu(a_s[ r0   *AS_STRIDE + c0 + 4]);
                af[mt][3] = fasu(a_s[(r0+8)*AS_STRIDE + c0 + 4]);
            }
            #pragma unroll
            for (int nt = 0; nt < 8; nt++) {
                int kk = ks*8 + qd;
                int nn = wn*64 + nt*8 + g;
                bf[nt][0] = fasu(b_s[ kk   *BS_STRIDE + nn]);
                bf[nt][1] = fasu(b_s[(kk+4)*BS_STRIDE + nn]);
            }
            #pragma unroll
            for (int mt = 0; mt < 2; mt++)
                #pragma unroll
                for (int nt = 0; nt < 8; nt++)
                    mma_tf32(acc[mt][nt][0], acc[mt][nt][1], acc[mt][nt][2], acc[mt][nt][3],
                             af[mt][0], af[mt][1], af[mt][2], af[mt][3],
                             bf[nt][0], bf[nt][1]);
        }
    }

    // epilogue: each (mt,nt) owns rows {r, r+8}, cols {c, c+1}
    #pragma unroll
    for (int mt = 0; mt < 2; mt++) {
        int r = rowBase + wm*32 + mt*16 + g;
        #pragma unroll
        for (int nt = 0; nt < 8; nt++) {
            int c = colBase + wn*64 + nt*8 + qd*2;
            float v00 = acc[mt][nt][0], v01 = acc[mt][nt][1];
            float v10 = acc[mt][nt][2], v11 = acc[mt][nt][3];
            if (EPI == 1 || EPI == 3) {
                float b0 = bias[c], b1 = bias[c+1];
                v00 += b0; v01 += b1; v10 += b0; v11 += b1;
            }
            if (EPI == 1) {
                v00 = fmaxf(v00, 0.f); v01 = fmaxf(v01, 0.f);
                v10 = fmaxf(v10, 0.f); v11 = fmaxf(v11, 0.f);
            }
            if (EPI >= 2) {
                float2 r0 = *(const float2*)(res + (size_t)r    *N + c);
                float2 r1 = *(const float2*)(res + (size_t)(r+8)*N + c);
                v00 += r0.x; v01 += r0.y; v10 += r1.x; v11 += r1.y;
            }
            float2 o0; o0.x = v00; o0.y = v01;
            float2 o1; o1.x = v10; o1.y = v11;
            *(float2*)(C + (size_t)r    *N + c) = o0;
            *(float2*)(C + (size_t)(r+8)*N + c) = o1;
        }
    }
    #undef LOAD_A
    #undef LOAD_B
}

// ---------------- Tensor-core flash attention ------------------------------
// BM=BN=64, DK=64. 4 warps, each warp owns 16 query rows.
#define FP 68
#define FA_SMEM (4*64*FP*4)
__global__ void __launch_bounds__(128)
fa_tc(const float* __restrict__ Q, const float* __restrict__ K,
      const float* __restrict__ V, float* __restrict__ O) {
    extern __shared__ float smx[];
    float* Qs = smx;
    float* Ks = Qs + 64*FP;
    float* Vs = Ks + 64*FP;
    float* Ps = Vs + 64*FP;

    int tid = threadIdx.x, lane = tid & 31, warp = tid >> 5;
    int g = lane >> 2, qd = lane & 3;
    int qt = blockIdx.x, bh = blockIdx.y;
    int b = bh >> 4, h = bh & 15;
    size_t base = (size_t)b * SS * DD + (size_t)h * DKK;

    // load Q tile, scaled by 1/sqrt(64)
    for (int c = tid; c < 64*16; c += 128) {
        int r = c >> 4, cc = (c & 15) * 4;
        float4 q4 = *(const float4*)(Q + base + (size_t)(qt*64 + r)*DD + cc);
        Qs[r*FP + cc + 0] = q4.x * 0.125f;
        Qs[r*FP + cc + 1] = q4.y * 0.125f;
        Qs[r*FP + cc + 2] = q4.z * 0.125f;
        Qs[r*FP + cc + 3] = q4.w * 0.125f;
    }

    float m0 = -1e30f, m1 = -1e30f, l0 = 0.f, l1 = 0.f;
    float o[8][4];
    #pragma unroll
    for (int nt = 0; nt < 8; nt++)
        #pragma unroll
        for (int e = 0; e < 4; e++) o[nt][e] = 0.f;

    int r0 = warp*16 + g;

    for (int kt = 0; kt < SS/64; kt++) {
        __syncthreads();   // prev PV done + initial Q load visible
        for (int c = tid; c < 64*16; c += 128) {
            int r = c >> 4, cc = (c & 15) * 4;
            size_t go = base + (size_t)(kt*64 + r)*DD + cc;
            cp_async16((unsigned int)__cvta_generic_to_shared(&Ks[r*FP + cc]), K + go);
            cp_async16((unsigned int)__cvta_generic_to_shared(&Vs[r*FP + cc]), V + go);
        }
        cp_commit(); cp_wait0();
        __syncthreads();

        // S = Q @ K^T
        float sc[8][4];
        #pragma unroll
        for (int nt = 0; nt < 8; nt++)
            #pragma unroll
            for (int e = 0; e < 4; e++) sc[nt][e] = 0.f;
        #pragma unroll
        for (int ks = 0; ks < 8; ks++) {
            int c0 = ks*8 + qd;
            unsigned int a0 = fasu(Qs[ r0   *FP + c0    ]);
            unsigned int a1 = fasu(Qs[(r0+8)*FP + c0    ]);
            unsigned int a2 = fasu(Qs[ r0   *FP + c0 + 4]);
            unsigned int a3 = fasu(Qs[(r0+8)*FP + c0 + 4]);
            #pragma unroll
            for (int nt = 0; nt < 8; nt++) {
                unsigned int b0 = fasu(Ks[(nt*8 + g)*FP + c0    ]);
                unsigned int b1 = fasu(Ks[(nt*8 + g)*FP + c0 + 4]);
                mma_tf32(sc[nt][0], sc[nt][1], sc[nt][2], sc[nt][3],
                         a0, a1, a2, a3, b0, b1);
            }
        }

        // online softmax (rows r0 and r0+8; 4 quad lanes hold a row's 16 cols)
        float mx0 = -1e30f, mx1 = -1e30f;
        #pragma unroll
        for (int nt = 0; nt < 8; nt++) {
            mx0 = fmaxf(mx0, fmaxf(sc[nt][0], sc[nt][1]));
            mx1 = fmaxf(mx1, fmaxf(sc[nt][2], sc[nt][3]));
        }
        mx0 = fmaxf(mx0, __shfl_xor_sync(0xffffffffu, mx0, 1));
        mx0 = fmaxf(mx0, __shfl_xor_sync(0xffffffffu, mx0, 2));
        mx1 = fmaxf(mx1, __shfl_xor_sync(0xffffffffu, mx1, 1));
        mx1 = fmaxf(mx1, __shfl_xor_sync(0xffffffffu, mx1, 2));
        float nm0 = fmaxf(m0, mx0), nm1 = fmaxf(m1, mx1);
        float sum0 = 0.f, sum1 = 0.f;
        #pragma unroll
        for (int nt = 0; nt < 8; nt++) {
            sc[nt][0] = __expf(sc[nt][0] - nm0);
            sc[nt][1] = __expf(sc[nt][1] - nm0);
            sc[nt][2] = __expf(sc[nt][2] - nm1);
            sc[nt][3] = __expf(sc[nt][3] - nm1);
            sum0 += sc[nt][0] + sc[nt][1];
            sum1 += sc[nt][2] + sc[nt][3];
        }
        sum0 += __shfl_xor_sync(0xffffffffu, sum0, 1);
        sum0 += __shfl_xor_sync(0xffffffffu, sum0, 2);
        sum1 += __shfl_xor_sync(0xffffffffu, sum1, 1);
        sum1 += __shfl_xor_sync(0xffffffffu, sum1, 2);
        float al0 = __expf(m0 - nm0), al1 = __expf(m1 - nm1);
        m0 = nm0; m1 = nm1;
        l0 = l0 * al0 + sum0;
        l1 = l1 * al1 + sum1;
        #pragma unroll
        for (int nt = 0; nt < 8; nt++) {
            o[nt][0] *= al0; o[nt][1] *= al0;
            o[nt][2] *= al1; o[nt][3] *= al1;
        }
        // stash P to smem for the PV mma
        #pragma unroll
        for (int nt = 0; nt < 8; nt++) {
            float2 p0; p0.x = sc[nt][0]; p0.y = sc[nt][1];
            float2 p1; p1.x = sc[nt][2]; p1.y = sc[nt][3];
            *(float2*)&Ps[ r0   *FP + nt*8 + qd*2] = p0;
            *(float2*)&Ps[(r0+8)*FP + nt*8 + qd*2] = p1;
        }
        __syncthreads();

        // O += P @ V
        #pragma unroll
        for (int ks = 0; ks < 8; ks++) {
            int c0 = ks*8 + qd;
            unsigned int a0 = fasu(Ps[ r0   *FP + c0    ]);
            unsigned int a1 = fasu(Ps[(r0+8)*FP + c0    ]);
            unsigned int a2 = fasu(Ps[ r0   *FP + c0 + 4]);
            unsigned int a3 = fasu(Ps[(r0+8)*FP + c0 + 4]);
            #pragma unroll
            for (int nt = 0; nt < 8; nt++) {
                unsigned int b0 = fasu(Vs[(ks*8 + qd  )*FP + nt*8 + g]);
                unsigned int b1 = fasu(Vs[(ks*8 + qd+4)*FP + nt*8 + g]);
                mma_tf32(o[nt][0], o[nt][1], o[nt][2], o[nt][3],
                         a0, a1, a2, a3, b0, b1);
            }
        }
    }

    // normalize and write out
    float inv0 = 1.f / l0, inv1 = 1.f / l1;
    size_t srow0 = (size_t)(b*SS + qt*64 + r0);
    #pragma unroll
    for (int nt = 0; nt < 8; nt++) {
        int c = h*DKK + nt*8 + qd*2;
        float2 o0; o0.x = o[nt][0]*inv0; o0.y = o[nt][1]*inv0;
        float2 o1; o1.x = o[nt][2]*inv1; o1.y = o[nt][3]*inv1;
        *(float2*)(O +  srow0     *DD + c) = o0;
        *(float2*)(O + (srow0 + 8)*DD + c) = o1;
    }
}

// ---------------- launch ----------------------------------------------------
extern "C" void kernel_launch(void* const* d_in, const int* in_sizes, int n_in,
                              void* d_out, int out_size) {
    (void)in_sizes; (void)n_in; (void)out_size;
    const float* x   = (const float*)d_in[0];
    const float* wq  = (const float*)d_in[1];
    const float* wk  = (const float*)d_in[2];
    const float* wv  = (const float*)d_in[3];
    const float* wo  = (const float*)d_in[4];
    const float* w1  = (const float*)d_in[5];
    const float* b1  = (const float*)d_in[6];
    const float* w2  = (const float*)d_in[7];
    const float* b2  = (const float*)d_in[8];
    const float* g1  = (const float*)d_in[9];
    const float* be1 = (const float*)d_in[10];
    const float* g2  = (const float*)d_in[11];
    const float* be2 = (const float*)d_in[12];
    float* out = (float*)d_out;

    float *h, *q, *k, *v, *attn, *x1, *h2, *ffn;
    cudaGetSymbolAddress((void**)&h,    g_h);
    cudaGetSymbolAddress((void**)&q,    g_q);
    cudaGetSymbolAddress((void**)&k,    g_k);
    cudaGetSymbolAddress((void**)&v,    g_v);
    cudaGetSymbolAddress((void**)&attn, g_attn);
    cudaGetSymbolAddress((void**)&x1,   g_x1);
    cudaGetSymbolAddress((void**)&h2,   g_h2);
    cudaGetSymbolAddress((void**)&ffn,  g_ffn);

    cudaFuncSetAttribute(tgemm<0>, cudaFuncAttributeMaxDynamicSharedMemorySize, GEMM_SMEM);
    cudaFuncSetAttribute(tgemm<1>, cudaFuncAttributeMaxDynamicSharedMemorySize, GEMM_SMEM);
    cudaFuncSetAttribute(tgemm<2>, cudaFuncAttributeMaxDynamicSharedMemorySize, GEMM_SMEM);
    cudaFuncSetAttribute(tgemm<3>, cudaFuncAttributeMaxDynamicSharedMemorySize, GEMM_SMEM);
    cudaFuncSetAttribute(fa_tc,    cudaFuncAttributeMaxDynamicSharedMemorySize, FA_SMEM);

    // 1) LN1
    ln_kernel<<<NTOK, 256>>>(x, g1, be1, h);
    // 2) QKV projections
    tgemm<0><<<dim3(DD/128, NTOK/128), 256, GEMM_SMEM>>>(h, wq, nullptr, nullptr, q, NTOK, DD, DD);
    tgemm<0><<<dim3(DD/128, NTOK/128), 256, GEMM_SMEM>>>(h, wk, nullptr, nullptr, k, NTOK, DD, DD);
    tgemm<0><<<dim3(DD/128, NTOK/128), 256, GEMM_SMEM>>>(h, wv, nullptr, nullptr, v, NTOK, DD, DD);
    // 3) attention
    fa_tc<<<dim3(SS/64, BBATCH*HH), 128, FA_SMEM>>>(q, k, v, attn);
    // 4) x1 = x + attn @ wo
    tgemm<2><<<dim3(DD/128, NTOK/128), 256, GEMM_SMEM>>>(attn, wo, nullptr, x, x1, NTOK, DD, DD);
    // 5) LN2
    ln_kernel<<<NTOK, 256>>>(x1, g2, be2, h2);
    // 6) ffn = relu(h2 @ w1 + b1)
    tgemm<1><<<dim3(DFFN/128, NTOK/128), 256, GEMM_SMEM>>>(h2, w1, b1, nullptr, ffn, NTOK, DFFN, DD);
    // 7) out = x1 + ffn @ w2 + b2
    tgemm<3><<<dim3(DD/128, NTOK/128), 256, GEMM_SMEM>>>(ffn, w2, b2, x1, out, NTOK, DD, DFFN);
}

// round 7
// speedup vs baseline: 3.4327x; 1.0493x over previous
#include <cuda_runtime.h>
#include <cstdint>
#include <math.h>

// Problem constants
#define BBATCH 4
#define SS 2048
#define DD 1024
#define HH 16
#define DKK 64
#define DFFN 4096
#define NTOK (BBATCH*SS)          // 8192
#define QKVW (3*DD)               // 3072
#define EPS 1e-5f

// ---------------- scratch (device globals) ---------------------------------
__device__ float g_h   [NTOK*DD];
__device__ float g_qkv [NTOK*QKVW];
__device__ float g_attn[NTOK*DD];
__device__ float g_x1  [NTOK*DD];
__device__ float g_h2  [NTOK*DD];
__device__ float g_ffn [NTOK*DFFN];
__device__ float g_wqkv[DD*QKVW];

// ---------------- PTX helpers ----------------------------------------------
__device__ __forceinline__ void cp_async16(unsigned int saddr, const void* gptr) {
    asm volatile("cp.async.ca.shared.global [%0], [%1], 16;\n" :: "r"(saddr), "l"(gptr));
}
__device__ __forceinline__ void cp_commit() { asm volatile("cp.async.commit_group;\n"); }
__device__ __forceinline__ void cp_wait0()  { asm volatile("cp.async.wait_group 0;\n"); }
__device__ __forceinline__ void cp_wait1()  { asm volatile("cp.async.wait_group 1;\n"); }

__device__ __forceinline__ void mma_tf32(float& c0, float& c1, float& c2, float& c3,
                                         unsigned int a0, unsigned int a1,
                                         unsigned int a2, unsigned int a3,
                                         unsigned int b0, unsigned int b1) {
    asm volatile("mma.sync.aligned.m16n8k8.row.col.f32.tf32.tf32.f32 "
                 "{%0,%1,%2,%3},{%4,%5,%6,%7},{%8,%9},{%0,%1,%2,%3};\n"
                 : "+f"(c0), "+f"(c1), "+f"(c2), "+f"(c3)
                 : "r"(a0), "r"(a1), "r"(a2), "r"(a3), "r"(b0), "r"(b1));
}
__device__ __forceinline__ unsigned int fasu(float x) { return __float_as_uint(x); }

// ---------------- pack wq|wk|wv into [D, 3D] --------------------------------
__global__ void pack_qkv(const float* __restrict__ wq, const float* __restrict__ wk,
                         const float* __restrict__ wv, float* __restrict__ out) {
    int idx = blockIdx.x * 256 + threadIdx.x;      // float4 index, 786432 total
    int r = idx / (QKVW/4), c4 = idx % (QKVW/4);
    int cc = c4 * 4;
    const float* s;
    if (cc < DD)            s = wq + (size_t)r*DD + cc;
    else if (cc < 2*DD)     s = wk + (size_t)r*DD + cc - DD;
    else                    s = wv + (size_t)r*DD + cc - 2*DD;
    *(float4*)(out + (size_t)r*QKVW + cc) = *(const float4*)s;
}

// ---------------- LayerNorm -------------------------------------------------
__global__ void ln_kernel(const float* __restrict__ x, const float* __restrict__ g,
                          const float* __restrict__ b, float* __restrict__ out) {
    int row = blockIdx.x;
    int tid = threadIdx.x;                       // 256 threads
    const float4* xr = (const float4*)(x + (size_t)row * DD);
    float4 v = xr[tid];
    float s  = v.x + v.y + v.z + v.w;
    float s2 = v.x*v.x + v.y*v.y + v.z*v.z + v.w*v.w;
    #pragma unroll
    for (int o = 16; o > 0; o >>= 1) {
        s  += __shfl_down_sync(0xffffffffu, s,  o);
        s2 += __shfl_down_sync(0xffffffffu, s2, o);
    }
    __shared__ float sa[8], sb[8];
    int w = tid >> 5, l = tid & 31;
    if (l == 0) { sa[w] = s; sb[w] = s2; }
    __syncthreads();
    if (w == 0) {
        s  = (l < 8) ? sa[l] : 0.f;
        s2 = (l < 8) ? sb[l] : 0.f;
        #pragma unroll
        for (int o = 4; o > 0; o >>= 1) {
            s  += __shfl_down_sync(0xffffffffu, s,  o);
            s2 += __shfl_down_sync(0xffffffffu, s2, o);
        }
        if (l == 0) { sa[0] = s; sb[0] = s2; }
    }
    __syncthreads();
    float mean = sa[0] * (1.0f / DD);
    float var  = sb[0] * (1.0f / DD) - mean * mean;
    float inv  = rsqrtf(var + EPS);
    float4 gg = ((const float4*)g)[tid];
    float4 bb = ((const float4*)b)[tid];
    float4 o4;
    o4.x = (v.x - mean) * inv * gg.x + bb.x;
    o4.y = (v.y - mean) * inv * gg.y + bb.y;
    o4.z = (v.z - mean) * inv * gg.z + bb.z;
    o4.w = (v.w - mean) * inv * gg.w + bb.w;
    ((float4*)(out + (size_t)row * DD))[tid] = o4;
}

// ---------------- TF32 tensor-core GEMM (128x256 tile, warp 64x64) ---------
// C[M,N] = A[M,K](row) @ B[K,N](row), fused epilogue.
#define AS_STR 36
#define BS_STR 264
#define AS_SZ (128*AS_STR)
#define BS_SZ (32*BS_STR)
#define G2_SMEM ((2*AS_SZ + 2*BS_SZ)*4)

template<int EPI>  // 0=none, 1=relu(C+bias), 2=C+res, 3=C+bias+res
__global__ void __launch_bounds__(256, 1)
tgemm2(const float* __restrict__ A, const float* __restrict__ B,
       const float* __restrict__ bias, const float* __restrict__ res,
       float* __restrict__ C, int M, int N, int K) {
    extern __shared__ float smx[];
    float* As0 = smx;
    float* As1 = smx + AS_SZ;
    float* Bs0 = smx + 2*AS_SZ;
    float* Bs1 = smx + 2*AS_SZ + BS_SZ;

    int tid = threadIdx.x, lane = tid & 31, warp = tid >> 5;
    int g = lane >> 2, qd = lane & 3;
    int wm = warp >> 2, wn = warp & 3;             // warp grid 2x4
    int rowBase = blockIdx.y * 128, colBase = blockIdx.x * 256;

    float acc[4][8][4];
    #pragma unroll
    for (int mt = 0; mt < 4; mt++)
        #pragma unroll
        for (int nt = 0; nt < 8; nt++)
            #pragma unroll
            for (int e = 0; e < 4; e++) acc[mt][nt][e] = 0.f;

    #define LOAD_A(dst, k0)                                                     \
        { _Pragma("unroll")                                                     \
          for (int i = 0; i < 4; i++) {                                         \
              int ch = tid + 256*i;                                             \
              int r = ch >> 3, kc = (ch & 7) * 4;                               \
              unsigned int s = (unsigned int)__cvta_generic_to_shared(&(dst)[r*AS_STR + kc]); \
              cp_async16(s, A + (size_t)(rowBase + r) * K + (k0) + kc);         \
          } }
    #define LOAD_B(dst, k0)                                                     \
        { _Pragma("unroll")                                                     \
          for (int i = 0; i < 8; i++) {                                         \
              int ch = tid + 256*i;                                             \
              int r = ch >> 6, nc = (ch & 63) * 4;                              \
              unsigned int s = (unsigned int)__cvta_generic_to_shared(&(dst)[r*BS_STR + nc]); \
              cp_async16(s, B + (size_t)((k0) + r) * N + colBase + nc);         \
          } }

    LOAD_A(As0, 0); LOAD_B(Bs0, 0); cp_commit();
    int nk = K >> 5;
    for (int kt = 0; kt < nk; kt++) {
        cp_wait0();
        __syncthreads();
        const float* a_s = (kt & 1) ? As1 : As0;
        const float* b_s = (kt & 1) ? Bs1 : Bs0;
        if (kt + 1 < nk) {
            float* an = (kt & 1) ? As0 : As1;
            float* bn = (kt & 1) ? Bs0 : Bs1;
            LOAD_A(an, (kt + 1) * 32); LOAD_B(bn, (kt + 1) * 32); cp_commit();
        }
        #pragma unroll
        for (int ks = 0; ks < 4; ks++) {
            unsigned int af[4][4], bf[8][2];
            int c0 = ks*8 + qd;
            #pragma unroll
            for (int mt = 0; mt < 4; mt++) {
                int r0 = wm*64 + mt*16 + g;
                af[mt][0] = fasu(a_s[ r0   *AS_STR + c0    ]);
                af[mt][1] = fasu(a_s[(r0+8)*AS_STR + c0    ]);
                af[mt][2] = fasu(a_s[ r0   *AS_STR + c0 + 4]);
                af[mt][3] = fasu(a_s[(r0+8)*AS_STR + c0 + 4]);
            }
            #pragma unroll
            for (int nt = 0; nt < 8; nt++) {
                int nn = wn*64 + nt*8 + g;
                bf[nt][0] = fasu(b_s[ c0   *BS_STR + nn]);
                bf[nt][1] = fasu(b_s[(c0+4)*BS_STR + nn]);
            }
            #pragma unroll
            for (int mt = 0; mt < 4; mt++)
                #pragma unroll
                for (int nt = 0; nt < 8; nt++)
                    mma_tf32(acc[mt][nt][0], acc[mt][nt][1], acc[mt][nt][2], acc[mt][nt][3],
                             af[mt][0], af[mt][1], af[mt][2], af[mt][3],
                             bf[nt][0], bf[nt][1]);
        }
        __syncthreads();
    }

    // epilogue: rows wm*64+mt*16+{g,g+8}, cols wn*64+nt*8+qd*2
    #pragma unroll
    for (int mt = 0; mt < 4; mt++) {
        int r = rowBase + wm*64 + mt*16 + g;
        #pragma unroll
        for (int nt = 0; nt < 8; nt++) {
            int c = colBase + wn*64 + nt*8 + qd*2;
            float v00 = acc[mt][nt][0], v01 = acc[mt][nt][1];
            float v10 = acc[mt][nt][2], v11 = acc[mt][nt][3];
            if (EPI == 1 || EPI == 3) {
                float b0 = bias[c], b1 = bias[c+1];
                v00 += b0; v01 += b1; v10 += b0; v11 += b1;
            }
            if (EPI == 1) {
                v00 = fmaxf(v00, 0.f); v01 = fmaxf(v01, 0.f);
                v10 = fmaxf(v10, 0.f); v11 = fmaxf(v11, 0.f);
            }
            if (EPI >= 2) {
                float2 r0 = *(const float2*)(res + (size_t)r    *N + c);
                float2 r1 = *(const float2*)(res + (size_t)(r+8)*N + c);
                v00 += r0.x; v01 += r0.y; v10 += r1.x; v11 += r1.y;
            }
            float2 o0; o0.x = v00; o0.y = v01;
            float2 o1; o1.x = v10; o1.y = v11;
            *(float2*)(C + (size_t)r    *N + c) = o0;
            *(float2*)(C + (size_t)(r+8)*N + c) = o1;
        }
    }
    #undef LOAD_A
    #undef LOAD_B
}

// ---------------- Tensor-core flash attention (packed QKV, dbuf KV) --------
#define FP 68
#define FA_SMEM (6*64*FP*4)
__global__ void __launch_bounds__(128)
fa_tc(const float* __restrict__ QKV, float* __restrict__ O) {
    extern __shared__ float smx[];
    float* Qs  = smx;
    float* Ks0 = Qs  + 64*FP;
    float* Ks1 = Ks0 + 64*FP;
    float* Vs0 = Ks1 + 64*FP;
    float* Vs1 = Vs0 + 64*FP;
    float* Ps  = Vs1 + 64*FP;

    int tid = threadIdx.x, lane = tid & 31, warp = tid >> 5;
    int g = lane >> 2, qd = lane & 3;
    int qt = blockIdx.x, bh = blockIdx.y;
    int b = bh >> 4, h = bh & 15;
    size_t base = (size_t)b * SS * QKVW + (size_t)h * DKK;
    const float* Qp = QKV + base;
    const float* Kp = QKV + base + DD;
    const float* Vp = QKV + base + 2*DD;

    // load Q tile, scaled by 1/sqrt(64)
    for (int c = tid; c < 64*16; c += 128) {
        int r = c >> 4, cc = (c & 15) * 4;
        float4 q4 = *(const float4*)(Qp + (size_t)(qt*64 + r)*QKVW + cc);
        Qs[r*FP + cc + 0] = q4.x * 0.125f;
        Qs[r*FP + cc + 1] = q4.y * 0.125f;
        Qs[r*FP + cc + 2] = q4.z * 0.125f;
        Qs[r*FP + cc + 3] = q4.w * 0.125f;
    }

    #define LOAD_KV(kb, vb, kt)                                                  \
        for (int c = tid; c < 64*16; c += 128) {                                 \
            int r = c >> 4, cc = (c & 15) * 4;                                   \
            size_t go = (size_t)((kt)*64 + r)*QKVW + cc;                         \
            cp_async16((unsigned int)__cvta_generic_to_shared(&(kb)[r*FP + cc]), Kp + go); \
            cp_async16((unsigned int)__cvta_generic_to_shared(&(vb)[r*FP + cc]), Vp + go); \
        }                                                                        \
        cp_commit();

    float m0 = -1e30f, m1 = -1e30f, l0 = 0.f, l1 = 0.f;
    float o[8][4];
    #pragma unroll
    for (int nt = 0; nt < 8; nt++)
        #pragma unroll
        for (int e = 0; e < 4; e++) o[nt][e] = 0.f;

    int r0 = warp*16 + g;
    const int NT = SS/64;

    LOAD_KV(Ks0, Vs0, 0);

    for (int kt = 0; kt < NT; kt++) {
        float* Ksb = (kt & 1) ? Ks1 : Ks0;
        float* Vsb = (kt & 1) ? Vs1 : Vs0;
        if (kt + 1 < NT) {
            float* kn = (kt & 1) ? Ks0 : Ks1;
            float* vn = (kt & 1) ? Vs0 : Vs1;
            LOAD_KV(kn, vn, kt + 1);
            cp_wait1();
        } else {
            cp_wait0();
        }
        __syncthreads();

        // S = Q @ K^T
        float sc[8][4];
        #pragma unroll
        for (int nt = 0; nt < 8; nt++)
            #pragma unroll
            for (int e = 0; e < 4; e++) sc[nt][e] = 0.f;
        #pragma unroll
        for (int ks = 0; ks < 8; ks++) {
            int c0 = ks*8 + qd;
            unsigned int a0 = fasu(Qs[ r0   *FP + c0    ]);
            unsigned int a1 = fasu(Qs[(r0+8)*FP + c0    ]);
            unsigned int a2 = fasu(Qs[ r0   *FP + c0 + 4]);
            unsigned int a3 = fasu(Qs[(r0+8)*FP + c0 + 4]);
            #pragma unroll
            for (int nt = 0; nt < 8; nt++) {
                unsigned int b0 = fasu(Ksb[(nt*8 + g)*FP + c0    ]);
                unsigned int b1 = fasu(Ksb[(nt*8 + g)*FP + c0 + 4]);
                mma_tf32(sc[nt][0], sc[nt][1], sc[nt][2], sc[nt][3],
                         a0, a1, a2, a3, b0, b1);
            }
        }

        // online softmax
        float mx0 = -1e30f, mx1 = -1e30f;
        #pragma unroll
        for (int nt = 0; nt < 8; nt++) {
            mx0 = fmaxf(mx0, fmaxf(sc[nt][0], sc[nt][1]));
            mx1 = fmaxf(mx1, fmaxf(sc[nt][2], sc[nt][3]));
        }
        mx0 = fmaxf(mx0, __shfl_xor_sync(0xffffffffu, mx0, 1));
        mx0 = fmaxf(mx0, __shfl_xor_sync(0xffffffffu, mx0, 2));
        mx1 = fmaxf(mx1, __shfl_xor_sync(0xffffffffu, mx1, 1));
        mx1 = fmaxf(mx1, __shfl_xor_sync(0xffffffffu, mx1, 2));
        float nm0 = fmaxf(m0, mx0), nm1 = fmaxf(m1, mx1);
        float sum0 = 0.f, sum1 = 0.f;
        #pragma unroll
        for (int nt = 0; nt < 8; nt++) {
            sc[nt][0] = __expf(sc[nt][0] - nm0);
            sc[nt][1] = __expf(sc[nt][1] - nm0);
            sc[nt][2] = __expf(sc[nt][2] - nm1);
            sc[nt][3] = __expf(sc[nt][3] - nm1);
            sum0 += sc[nt][0] + sc[nt][1];
            sum1 += sc[nt][2] + sc[nt][3];
        }
        sum0 += __shfl_xor_sync(0xffffffffu, sum0, 1);
        sum0 += __shfl_xor_sync(0xffffffffu, sum0, 2);
        sum1 += __shfl_xor_sync(0xffffffffu, sum1, 1);
        sum1 += __shfl_xor_sync(0xffffffffu, sum1, 2);
        float al0 = __expf(m0 - nm0), al1 = __expf(m1 - nm1);
        m0 = nm0; m1 = nm1;
        l0 = l0 * al0 + sum0;
        l1 = l1 * al1 + sum1;
        #pragma unroll
        for (int nt = 0; nt < 8; nt++) {
            o[nt][0] *= al0; o[nt][1] *= al0;
            o[nt][2] *= al1; o[nt][3] *= al1;
        }
        #pragma unroll
        for (int nt = 0; nt < 8; nt++) {
            float2 p0; p0.x = sc[nt][0]; p0.y = sc[nt][1];
            float2 p1; p1.x = sc[nt][2]; p1.y = sc[nt][3];
            *(float2*)&Ps[ r0   *FP + nt*8 + qd*2] = p0;
            *(float2*)&Ps[(r0+8)*FP + nt*8 + qd*2] = p1;
        }
        __syncthreads();

        // O += P @ V
        #pragma unroll
        for (int ks = 0; ks < 8; ks++) {
            int c0 = ks*8 + qd;
            unsigned int a0 = fasu(Ps[ r0   *FP + c0    ]);
            unsigned int a1 = fasu(Ps[(r0+8)*FP + c0    ]);
            unsigned int a2 = fasu(Ps[ r0   *FP + c0 + 4]);
            unsigned int a3 = fasu(Ps[(r0+8)*FP + c0 + 4]);
            #pragma unroll
            for (int nt = 0; nt < 8; nt++) {
                unsigned int b0 = fasu(Vsb[(ks*8 + qd  )*FP + nt*8 + g]);
                unsigned int b1 = fasu(Vsb[(ks*8 + qd+4)*FP + nt*8 + g]);
                mma_tf32(o[nt][0], o[nt][1], o[nt][2], o[nt][3],
                         a0, a1, a2, a3, b0, b1);
            }
        }
        __syncthreads();   // protect smem buffers before next stage load/overwrite
    }
    #undef LOAD_KV

    float inv0 = 1.f / l0, inv1 = 1.f / l1;
    size_t srow0 = (size_t)(b*SS + qt*64 + r0);
    #pragma unroll
    for (int nt = 0; nt < 8; nt++) {
        int c = h*DKK + nt*8 + qd*2;
        float2 o0; o0.x = o[nt][0]*inv0; o0.y = o[nt][1]*inv0;
        float2 o1; o1.x = o[nt][2]*inv1; o1.y = o[nt][3]*inv1;
        *(float2*)(O +  srow0     *DD + c) = o0;
        *(float2*)(O + (srow0 + 8)*DD + c) = o1;
    }
}

// ---------------- launch ----------------------------------------------------
extern "C" void kernel_launch(void* const* d_in, const int* in_sizes, int n_in,
                              void* d_out, int out_size) {
    (void)in_sizes; (void)n_in; (void)out_size;
    const float* x   = (const float*)d_in[0];
    const float* wq  = (const float*)d_in[1];
    const float* wk  = (const float*)d_in[2];
    const float* wv  = (const float*)d_in[3];
    const float* wo  = (const float*)d_in[4];
    const float* w1  = (const float*)d_in[5];
    const float* b1  = (const float*)d_in[6];
    const float* w2  = (const float*)d_in[7];
    const float* b2  = (const float*)d_in[8];
    const float* g1  = (const float*)d_in[9];
    const float* be1 = (const float*)d_in[10];
    const float* g2  = (const float*)d_in[11];
    const float* be2 = (const float*)d_in[12];
    float* out = (float*)d_out;

    float *h, *qkv, *attn, *x1, *h2, *ffn, *wqkv;
    cudaGetSymbolAddress((void**)&h,    g_h);
    cudaGetSymbolAddress((void**)&qkv,  g_qkv);
    cudaGetSymbolAddress((void**)&attn, g_attn);
    cudaGetSymbolAddress((void**)&x1,   g_x1);
    cudaGetSymbolAddress((void**)&h2,   g_h2);
    cudaGetSymbolAddress((void**)&ffn,  g_ffn);
    cudaGetSymbolAddress((void**)&wqkv, g_wqkv);

    cudaFuncSetAttribute(tgemm2<0>, cudaFuncAttributeMaxDynamicSharedMemorySize, G2_SMEM);
    cudaFuncSetAttribute(tgemm2<1>, cudaFuncAttributeMaxDynamicSharedMemorySize, G2_SMEM);
    cudaFuncSetAttribute(tgemm2<2>, cudaFuncAttributeMaxDynamicSharedMemorySize, G2_SMEM);
    cudaFuncSetAttribute(tgemm2<3>, cudaFuncAttributeMaxDynamicSharedMemorySize, G2_SMEM);
    cudaFuncSetAttribute(fa_tc,     cudaFuncAttributeMaxDynamicSharedMemorySize, FA_SMEM);

    // 0) pack weights
    pack_qkv<<<(DD*QKVW/4)/256, 256>>>(wq, wk, wv, wqkv);
    // 1) LN1
    ln_kernel<<<NTOK, 256>>>(x, g1, be1, h);
    // 2) fused QKV projection
    tgemm2<0><<<dim3(QKVW/256, NTOK/128), 256, G2_SMEM>>>(h, wqkv, nullptr, nullptr, qkv, NTOK, QKVW, DD);
    // 3) attention
    fa_tc<<<dim3(SS/64, BBATCH*HH), 128, FA_SMEM>>>(qkv, attn);
    // 4) x1 = x + attn @ wo
    tgemm2<2><<<dim3(DD/256, NTOK/128), 256, G2_SMEM>>>(attn, wo, nullptr, x, x1, NTOK, DD, DD);
    // 5) LN2
    ln_kernel<<<NTOK, 256>>>(x1, g2, be2, h2);
    // 6) ffn = relu(h2 @ w1 + b1)
    tgemm2<1><<<dim3(DFFN/256, NTOK/128), 256, G2_SMEM>>>(h2, w1, b1, nullptr, ffn, NTOK, DFFN, DD);
    // 7) out = x1 + ffn @ w2 + b2
    tgemm2<3><<<dim3(DD/256, NTOK/128), 256, G2_SMEM>>>(ffn, w2, b2, x1, out, NTOK, DD, DFFN);
}

// round 11
// speedup vs baseline: 3.8874x; 1.1325x over previous
#include <cuda_runtime.h>
#include <cstdint>
#include <math.h>

// Problem constants
#define BBATCH 4
#define SS 2048
#define DD 1024
#define HH 16
#define DKK 64
#define DFFN 4096
#define NTOK (BBATCH*SS)          // 8192
#define QKVW (3*DD)               // 3072
#define EPS 1e-5f

// ---------------- scratch (device globals) ---------------------------------
__device__ float g_h   [NTOK*DD];
__device__ float g_qkv [NTOK*QKVW];
__device__ float g_attn[NTOK*DD];
__device__ float g_x1  [NTOK*DD];
__device__ float g_h2  [NTOK*DD];
__device__ float g_ffn [NTOK*DFFN];
__device__ float g_wqkv[DD*QKVW];

// ---------------- PTX helpers ----------------------------------------------
__device__ __forceinline__ void cp_async16(unsigned int saddr, const void* gptr) {
    asm volatile("cp.async.ca.shared.global [%0], [%1], 16;\n" :: "r"(saddr), "l"(gptr));
}
__device__ __forceinline__ void cp_commit() { asm volatile("cp.async.commit_group;\n"); }
__device__ __forceinline__ void cp_wait0()  { asm volatile("cp.async.wait_group 0;\n"); }
__device__ __forceinline__ void cp_wait1()  { asm volatile("cp.async.wait_group 1;\n"); }

__device__ __forceinline__ void mma_tf32(float& c0, float& c1, float& c2, float& c3,
                                         unsigned int a0, unsigned int a1,
                                         unsigned int a2, unsigned int a3,
                                         unsigned int b0, unsigned int b1) {
    asm volatile("mma.sync.aligned.m16n8k8.row.col.f32.tf32.tf32.f32 "
                 "{%0,%1,%2,%3},{%4,%5,%6,%7},{%8,%9},{%0,%1,%2,%3};\n"
                 : "+f"(c0), "+f"(c1), "+f"(c2), "+f"(c3)
                 : "r"(a0), "r"(a1), "r"(a2), "r"(a3), "r"(b0), "r"(b1));
}
__device__ __forceinline__ unsigned int fasu(float x) { return __float_as_uint(x); }

// ---------------- pack wq|wk|wv into [D, 3D] --------------------------------
__global__ void pack_qkv(const float* __restrict__ wq, const float* __restrict__ wk,
                         const float* __restrict__ wv, float* __restrict__ out) {
    int idx = blockIdx.x * 256 + threadIdx.x;      // float4 index
    int r = idx / (QKVW/4), c4 = idx % (QKVW/4);
    int cc = c4 * 4;
    const float* s;
    if (cc < DD)            s = wq + (size_t)r*DD + cc;
    else if (cc < 2*DD)     s = wk + (size_t)r*DD + cc - DD;
    else                    s = wv + (size_t)r*DD + cc - 2*DD;
    *(float4*)(out + (size_t)r*QKVW + cc) = *(const float4*)s;
}

// ---------------- LayerNorm -------------------------------------------------
__global__ void ln_kernel(const float* __restrict__ x, const float* __restrict__ g,
                          const float* __restrict__ b, float* __restrict__ out) {
    int row = blockIdx.x;
    int tid = threadIdx.x;                       // 256 threads
    const float4* xr = (const float4*)(x + (size_t)row * DD);
    float4 v = xr[tid];
    float s  = v.x + v.y + v.z + v.w;
    float s2 = v.x*v.x + v.y*v.y + v.z*v.z + v.w*v.w;
    #pragma unroll
    for (int o = 16; o > 0; o >>= 1) {
        s  += __shfl_down_sync(0xffffffffu, s,  o);
        s2 += __shfl_down_sync(0xffffffffu, s2, o);
    }
    __shared__ float sa[8], sb[8];
    int w = tid >> 5, l = tid & 31;
    if (l == 0) { sa[w] = s; sb[w] = s2; }
    __syncthreads();
    if (w == 0) {
        s  = (l < 8) ? sa[l] : 0.f;
        s2 = (l < 8) ? sb[l] : 0.f;
        #pragma unroll
        for (int o = 4; o > 0; o >>= 1) {
            s  += __shfl_down_sync(0xffffffffu, s,  o);
            s2 += __shfl_down_sync(0xffffffffu, s2, o);
        }
        if (l == 0) { sa[0] = s; sb[0] = s2; }
    }
    __syncthreads();
    float mean = sa[0] * (1.0f / DD);
    float var  = sb[0] * (1.0f / DD) - mean * mean;
    float inv  = rsqrtf(var + EPS);
    float4 gg = ((const float4*)g)[tid];
    float4 bb = ((const float4*)b)[tid];
    float4 o4;
    o4.x = (v.x - mean) * inv * gg.x + bb.x;
    o4.y = (v.y - mean) * inv * gg.y + bb.y;
    o4.z = (v.z - mean) * inv * gg.z + bb.z;
    o4.w = (v.w - mean) * inv * gg.w + bb.w;
    ((float4*)(out + (size_t)row * DD))[tid] = o4;
}

// ---------------- TF32 tensor-core GEMM (128x256 tile, warp 64x64) ---------
#define AS_STR 36
#define BS_STR 264
#define AS_SZ (128*AS_STR)
#define BS_SZ (32*BS_STR)
#define G2_SMEM ((2*AS_SZ + 2*BS_SZ)*4)

template<int EPI>  // 0=none, 1=relu(C+bias), 2=C+res, 3=C+bias+res
__global__ void __launch_bounds__(256, 1)
tgemm2(const float* __restrict__ A, const float* __restrict__ B,
       const float* __restrict__ bias, const float* __restrict__ res,
       float* __restrict__ C, int M, int N, int K) {
    extern __shared__ float smx[];
    float* As0 = smx;
    float* As1 = smx + AS_SZ;
    float* Bs0 = smx + 2*AS_SZ;
    float* Bs1 = smx + 2*AS_SZ + BS_SZ;

    int tid = threadIdx.x, lane = tid & 31, warp = tid >> 5;
    int g = lane >> 2, qd = lane & 3;
    int wm = warp >> 2, wn = warp & 3;             // warp grid 2x4
    int rowBase = blockIdx.y * 128, colBase = blockIdx.x * 256;

    float acc[4][8][4];
    #pragma unroll
    for (int mt = 0; mt < 4; mt++)
        #pragma unroll
        for (int nt = 0; nt < 8; nt++)
            #pragma unroll
            for (int e = 0; e < 4; e++) acc[mt][nt][e] = 0.f;

    #define LOAD_A(dst, k0)                                                     \
        { _Pragma("unroll")                                                     \
          for (int i = 0; i < 4; i++) {                                         \
              int ch = tid + 256*i;                                             \
              int r = ch >> 3, kc = (ch & 7) * 4;                               \
              unsigned int s = (unsigned int)__cvta_generic_to_shared(&(dst)[r*AS_STR + kc]); \
              cp_async16(s, A + (size_t)(rowBase + r) * K + (k0) + kc);         \
          } }
    #define LOAD_B(dst, k0)                                                     \
        { _Pragma("unroll")                                                     \
          for (int i = 0; i < 8; i++) {                                         \
              int ch = tid + 256*i;                                             \
              int r = ch >> 6, nc = (ch & 63) * 4;                              \
              unsigned int s = (unsigned int)__cvta_generic_to_shared(&(dst)[r*BS_STR + nc]); \
              cp_async16(s, B + (size_t)((k0) + r) * N + colBase + nc);         \
          } }

    LOAD_A(As0, 0); LOAD_B(Bs0, 0); cp_commit();
    int nk = K >> 5;
    for (int kt = 0; kt < nk; kt++) {
        cp_wait0();
        __syncthreads();
        const float* a_s = (kt & 1) ? As1 : As0;
        const float* b_s = (kt & 1) ? Bs1 : Bs0;
        if (kt + 1 < nk) {
            float* an = (kt & 1) ? As0 : As1;
            float* bn = (kt & 1) ? Bs0 : Bs1;
            LOAD_A(an, (kt + 1) * 32); LOAD_B(bn, (kt + 1) * 32); cp_commit();
        }
        #pragma unroll
        for (int ks = 0; ks < 4; ks++) {
            unsigned int af[4][4], bf[8][2];
            int c0 = ks*8 + qd;
            #pragma unroll
            for (int mt = 0; mt < 4; mt++) {
                int r0 = wm*64 + mt*16 + g;
                af[mt][0] = fasu(a_s[ r0   *AS_STR + c0    ]);
                af[mt][1] = fasu(a_s[(r0+8)*AS_STR + c0    ]);
                af[mt][2] = fasu(a_s[ r0   *AS_STR + c0 + 4]);
                af[mt][3] = fasu(a_s[(r0+8)*AS_STR + c0 + 4]);
            }
            #pragma unroll
            for (int nt = 0; nt < 8; nt++) {
                int nn = wn*64 + nt*8 + g;
                bf[nt][0] = fasu(b_s[ c0   *BS_STR + nn]);
                bf[nt][1] = fasu(b_s[(c0+4)*BS_STR + nn]);
            }
            #pragma unroll
            for (int mt = 0; mt < 4; mt++)
                #pragma unroll
                for (int nt = 0; nt < 8; nt++)
                    mma_tf32(acc[mt][nt][0], acc[mt][nt][1], acc[mt][nt][2], acc[mt][nt][3],
                             af[mt][0], af[mt][1], af[mt][2], af[mt][3],
                             bf[nt][0], bf[nt][1]);
        }
        __syncthreads();
    }

    #pragma unroll
    for (int mt = 0; mt < 4; mt++) {
        int r = rowBase + wm*64 + mt*16 + g;
        #pragma unroll
        for (int nt = 0; nt < 8; nt++) {
            int c = colBase + wn*64 + nt*8 + qd*2;
            float v00 = acc[mt][nt][0], v01 = acc[mt][nt][1];
            float v10 = acc[mt][nt][2], v11 = acc[mt][nt][3];
            if (EPI == 1 || EPI == 3) {
                float b0 = bias[c], b1 = bias[c+1];
                v00 += b0; v01 += b1; v10 += b0; v11 += b1;
            }
            if (EPI == 1) {
                v00 = fmaxf(v00, 0.f); v01 = fmaxf(v01, 0.f);
                v10 = fmaxf(v10, 0.f); v11 = fmaxf(v11, 0.f);
            }
            if (EPI >= 2) {
                float2 r0 = *(const float2*)(res + (size_t)r    *N + c);
                float2 r1 = *(const float2*)(res + (size_t)(r+8)*N + c);
                v00 += r0.x; v01 += r0.y; v10 += r1.x; v11 += r1.y;
            }
            float2 o0; o0.x = v00; o0.y = v01;
            float2 o1; o1.x = v10; o1.y = v11;
            *(float2*)(C + (size_t)r    *N + c) = o0;
            *(float2*)(C + (size_t)(r+8)*N + c) = o1;
        }
    }
    #undef LOAD_A
    #undef LOAD_B
}

// ---------------- Flash attention v2: BM=128, 256 thr, Q in regs -----------
// smem: QsPs (128xFP, Q staging reused as P) + K0,K1,V0,V1 (64xFP each)
#define FP 68
#define FA_SMEM ((128*FP + 4*64*FP)*4)     // 104448 bytes -> 2 CTAs/SM
__global__ void __launch_bounds__(256, 2)
fa_tc(const float* __restrict__ QKV, float* __restrict__ O) {
    extern __shared__ float smx[];
    float* QsPs = smx;                    // 128*FP: Q staging, then P
    float* Ks0  = smx  + 128*FP;
    float* Ks1  = Ks0  + 64*FP;
    float* Vs0  = Ks1  + 64*FP;
    float* Vs1  = Vs0  + 64*FP;

    int tid = threadIdx.x, lane = tid & 31, warp = tid >> 5;   // 8 warps
    int g = lane >> 2, qd = lane & 3;
    int qt = blockIdx.x, bh = blockIdx.y;
    int b = bh >> 4, h = bh & 15;
    size_t base = (size_t)b * SS * QKVW + (size_t)h * DKK;
    const float* Qp = QKV + base;
    const float* Kp = QKV + base + DD;
    const float* Vp = QKV + base + 2*DD;

    #define LOAD_KV(kb, vb, kt)                                                  \
        for (int c = tid; c < 64*16; c += 256) {                                 \
            int r = c >> 4, cc = (c & 15) * 4;                                   \
            size_t go = (size_t)((kt)*64 + r)*QKVW + cc;                         \
            cp_async16((unsigned int)__cvta_generic_to_shared(&(kb)[r*FP + cc]), Kp + go); \
            cp_async16((unsigned int)__cvta_generic_to_shared(&(vb)[r*FP + cc]), Vp + go); \
        }                                                                        \
        cp_commit();

    // kick off first KV load, then stage Q (128 rows)
    LOAD_KV(Ks0, Vs0, 0);
    for (int c = tid; c < 128*16; c += 256) {
        int r = c >> 4, cc = (c & 15) * 4;
        float4 q4 = *(const float4*)(Qp + (size_t)(qt*128 + r)*QKVW + cc);
        QsPs[r*FP + cc + 0] = q4.x * 0.125f;
        QsPs[r*FP + cc + 1] = q4.y * 0.125f;
        QsPs[r*FP + cc + 2] = q4.z * 0.125f;
        QsPs[r*FP + cc + 3] = q4.w * 0.125f;
    }
    __syncthreads();

    int r0 = warp*16 + g;     // this warp's 16 query rows: r0..r0+15 (via +8)
    // extract Q fragments to registers (reused all 32 iterations)
    unsigned int qf[8][4];
    #pragma unroll
    for (int ks = 0; ks < 8; ks++) {
        int c0 = ks*8 + qd;
        qf[ks][0] = fasu(QsPs[ r0   *FP + c0    ]);
        qf[ks][1] = fasu(QsPs[(r0+8)*FP + c0    ]);
        qf[ks][2] = fasu(QsPs[ r0   *FP + c0 + 4]);
        qf[ks][3] = fasu(QsPs[(r0+8)*FP + c0 + 4]);
    }
    float* Ps = QsPs;         // alias: Q staging buffer becomes P

    float m0 = -1e30f, m1 = -1e30f, l0 = 0.f, l1 = 0.f;
    float o[8][4];
    #pragma unroll
    for (int nt = 0; nt < 8; nt++)
        #pragma unroll
        for (int e = 0; e < 4; e++) o[nt][e] = 0.f;

    const int NT = SS/64;
    for (int kt = 0; kt < NT; kt++) {
        float* Ksb = (kt & 1) ? Ks1 : Ks0;
        float* Vsb = (kt & 1) ? Vs1 : Vs0;
        if (kt + 1 < NT) {
            float* kn = (kt & 1) ? Ks0 : Ks1;
            float* vn = (kt & 1) ? Vs0 : Vs1;
            LOAD_KV(kn, vn, kt + 1);
            cp_wait1();
        } else {
            cp_wait0();
        }
        __syncthreads();   // KV ready; also guards Q-extract (kt=0) and prev-iter P/KV reuse

        // S = Q @ K^T
        float sc[8][4];
        #pragma unroll
        for (int nt = 0; nt < 8; nt++)
            #pragma unroll
            for (int e = 0; e < 4; e++) sc[nt][e] = 0.f;
        #pragma unroll
        for (int ks = 0; ks < 8; ks++) {
            int c0 = ks*8 + qd;
            #pragma unroll
            for (int nt = 0; nt < 8; nt++) {
                unsigned int b0 = fasu(Ksb[(nt*8 + g)*FP + c0    ]);
                unsigned int b1 = fasu(Ksb[(nt*8 + g)*FP + c0 + 4]);
                mma_tf32(sc[nt][0], sc[nt][1], sc[nt][2], sc[nt][3],
                         qf[ks][0], qf[ks][1], qf[ks][2], qf[ks][3], b0, b1);
            }
        }

        // online softmax (rows r0, r0+8)
        float mx0 = -1e30f, mx1 = -1e30f;
        #pragma unroll
        for (int nt = 0; nt < 8; nt++) {
            mx0 = fmaxf(mx0, fmaxf(sc[nt][0], sc[nt][1]));
            mx1 = fmaxf(mx1, fmaxf(sc[nt][2], sc[nt][3]));
        }
        mx0 = fmaxf(mx0, __shfl_xor_sync(0xffffffffu, mx0, 1));
        mx0 = fmaxf(mx0, __shfl_xor_sync(0xffffffffu, mx0, 2));
        mx1 = fmaxf(mx1, __shfl_xor_sync(0xffffffffu, mx1, 1));
        mx1 = fmaxf(mx1, __shfl_xor_sync(0xffffffffu, mx1, 2));
        float nm0 = fmaxf(m0, mx0), nm1 = fmaxf(m1, mx1);
        float sum0 = 0.f, sum1 = 0.f;
        #pragma unroll
        for (int nt = 0; nt < 8; nt++) {
            sc[nt][0] = __expf(sc[nt][0] - nm0);
            sc[nt][1] = __expf(sc[nt][1] - nm0);
            sc[nt][2] = __expf(sc[nt][2] - nm1);
            sc[nt][3] = __expf(sc[nt][3] - nm1);
            sum0 += sc[nt][0] + sc[nt][1];
            sum1 += sc[nt][2] + sc[nt][3];
        }
        sum0 += __shfl_xor_sync(0xffffffffu, sum0, 1);
        sum0 += __shfl_xor_sync(0xffffffffu, sum0, 2);
        sum1 += __shfl_xor_sync(0xffffffffu, sum1, 1);
        sum1 += __shfl_xor_sync(0xffffffffu, sum1, 2);
        float al0 = __expf(m0 - nm0), al1 = __expf(m1 - nm1);
        m0 = nm0; m1 = nm1;
        l0 = l0 * al0 + sum0;
        l1 = l1 * al1 + sum1;
        #pragma unroll
        for (int nt = 0; nt < 8; nt++) {
            o[nt][0] *= al0; o[nt][1] *= al0;
            o[nt][2] *= al1; o[nt][3] *= al1;
        }
        // stash P (warp-private rows) — warp-level sync only
        #pragma unroll
        for (int nt = 0; nt < 8; nt++) {
            float2 p0; p0.x = sc[nt][0]; p0.y = sc[nt][1];
            float2 p1; p1.x = sc[nt][2]; p1.y = sc[nt][3];
            *(float2*)&Ps[ r0   *FP + nt*8 + qd*2] = p0;
            *(float2*)&Ps[(r0+8)*FP + nt*8 + qd*2] = p1;
        }
        __syncwarp();

        // O += P @ V
        #pragma unroll
        for (int ks = 0; ks < 8; ks++) {
            int c0 = ks*8 + qd;
            unsigned int a0 = fasu(Ps[ r0   *FP + c0    ]);
            unsigned int a1 = fasu(Ps[(r0+8)*FP + c0    ]);
            unsigned int a2 = fasu(Ps[ r0   *FP + c0 + 4]);
            unsigned int a3 = fasu(Ps[(r0+8)*FP + c0 + 4]);
            #pragma unroll
            for (int nt = 0; nt < 8; nt++) {
                unsigned int b0 = fasu(Vsb[(ks*8 + qd  )*FP + nt*8 + g]);
                unsigned int b1 = fasu(Vsb[(ks*8 + qd+4)*FP + nt*8 + g]);
                mma_tf32(o[nt][0], o[nt][1], o[nt][2], o[nt][3],
                         a0, a1, a2, a3, b0, b1);
            }
        }
        __syncthreads();   // all warps done with Ksb/Vsb before next-iter load overwrites
    }
    #undef LOAD_KV

    float inv0 = 1.f / l0, inv1 = 1.f / l1;
    size_t srow0 = (size_t)(b*SS + qt*128 + r0);
    #pragma unroll
    for (int nt = 0; nt < 8; nt++) {
        int c = h*DKK + nt*8 + qd*2;
        float2 o0; o0.x = o[nt][0]*inv0; o0.y = o[nt][1]*inv0;
        float2 o1; o1.x = o[nt][2]*inv1; o1.y = o[nt][3]*inv1;
        *(float2*)(O +  srow0     *DD + c) = o0;
        *(float2*)(O + (srow0 + 8)*DD + c) = o1;
    }
}

// ---------------- launch ----------------------------------------------------
extern "C" void kernel_launch(void* const* d_in, const int* in_sizes, int n_in,
                              void* d_out, int out_size) {
    (void)in_sizes; (void)n_in; (void)out_size;
    const float* x   = (const float*)d_in[0];
    const float* wq  = (const float*)d_in[1];
    const float* wk  = (const float*)d_in[2];
    const float* wv  = (const float*)d_in[3];
    const float* wo  = (const float*)d_in[4];
    const float* w1  = (const float*)d_in[5];
    const float* b1  = (const float*)d_in[6];
    const float* w2  = (const float*)d_in[7];
    const float* b2  = (const float*)d_in[8];
    const float* g1  = (const float*)d_in[9];
    const float* be1 = (const float*)d_in[10];
    const float* g2  = (const float*)d_in[11];
    const float* be2 = (const float*)d_in[12];
    float* out = (float*)d_out;

    float *h, *qkv, *attn, *x1, *h2, *ffn, *wqkv;
    cudaGetSymbolAddress((void**)&h,    g_h);
    cudaGetSymbolAddress((void**)&qkv,  g_qkv);
    cudaGetSymbolAddress((void**)&attn, g_attn);
    cudaGetSymbolAddress((void**)&x1,   g_x1);
    cudaGetSymbolAddress((void**)&h2,   g_h2);
    cudaGetSymbolAddress((void**)&ffn,  g_ffn);
    cudaGetSymbolAddress((void**)&wqkv, g_wqkv);

    cudaFuncSetAttribute(tgemm2<0>, cudaFuncAttributeMaxDynamicSharedMemorySize, G2_SMEM);
    cudaFuncSetAttribute(tgemm2<1>, cudaFuncAttributeMaxDynamicSharedMemorySize, G2_SMEM);
    cudaFuncSetAttribute(tgemm2<2>, cudaFuncAttributeMaxDynamicSharedMemorySize, G2_SMEM);
    cudaFuncSetAttribute(tgemm2<3>, cudaFuncAttributeMaxDynamicSharedMemorySize, G2_SMEM);
    cudaFuncSetAttribute(fa_tc,     cudaFuncAttributeMaxDynamicSharedMemorySize, FA_SMEM);

    // 0) pack weights
    pack_qkv<<<(DD*QKVW/4)/256, 256>>>(wq, wk, wv, wqkv);
    // 1) LN1
    ln_kernel<<<NTOK, 256>>>(x, g1, be1, h);
    // 2) fused QKV projection
    tgemm2<0><<<dim3(QKVW/256, NTOK/128), 256, G2_SMEM>>>(h, wqkv, nullptr, nullptr, qkv, NTOK, QKVW, DD);
    // 3) attention (BM=128)
    fa_tc<<<dim3(SS/128, BBATCH*HH), 256, FA_SMEM>>>(qkv, attn);
    // 4) x1 = x + attn @ wo
    tgemm2<2><<<dim3(DD/256, NTOK/128), 256, G2_SMEM>>>(attn, wo, nullptr, x, x1, NTOK, DD, DD);
    // 5) LN2
    ln_kernel<<<NTOK, 256>>>(x1, g2, be2, h2);
    // 6) ffn = relu(h2 @ w1 + b1)
    tgemm2<1><<<dim3(DFFN/256, NTOK/128), 256, G2_SMEM>>>(h2, w1, b1, nullptr, ffn, NTOK, DFFN, DD);
    // 7) out = x1 + ffn @ w2 + b2
    tgemm2<3><<<dim3(DD/256, NTOK/128), 256, G2_SMEM>>>(ffn, w2, b2, x1, out, NTOK, DD, DFFN);
}

// round 15
// speedup vs baseline: 3.9837x; 1.0248x over previous
#include <cuda_runtime.h>
#include <cstdint>
#include <math.h>

// Problem constants
#define BBATCH 4
#define SS 2048
#define DD 1024
#define HH 16
#define DKK 64
#define DFFN 4096
#define NTOK (BBATCH*SS)          // 8192
#define QKVW (3*DD)               // 3072
#define EPS 1e-5f

// ---------------- scratch (device globals) ---------------------------------
__device__ float g_h   [NTOK*DD];
__device__ float g_qkv [NTOK*QKVW];
__device__ float g_attn[NTOK*DD];
__device__ float g_x1  [NTOK*DD];
__device__ float g_h2  [NTOK*DD];
__device__ float g_ffn [NTOK*DFFN];
__device__ float g_wqkv[DD*QKVW];

// ---------------- PTX helpers ----------------------------------------------
__device__ __forceinline__ void cp_async16(unsigned int saddr, const void* gptr) {
    asm volatile("cp.async.ca.shared.global [%0], [%1], 16;\n" :: "r"(saddr), "l"(gptr));
}
__device__ __forceinline__ void cp_commit() { asm volatile("cp.async.commit_group;\n"); }
__device__ __forceinline__ void cp_wait0()  { asm volatile("cp.async.wait_group 0;\n"); }

__device__ __forceinline__ void mma_tf32(float& c0, float& c1, float& c2, float& c3,
                                         unsigned int a0, unsigned int a1,
                                         unsigned int a2, unsigned int a3,
                                         unsigned int b0, unsigned int b1) {
    asm volatile("mma.sync.aligned.m16n8k8.row.col.f32.tf32.tf32.f32 "
                 "{%0,%1,%2,%3},{%4,%5,%6,%7},{%8,%9},{%0,%1,%2,%3};\n"
                 : "+f"(c0), "+f"(c1), "+f"(c2), "+f"(c3)
                 : "r"(a0), "r"(a1), "r"(a2), "r"(a3), "r"(b0), "r"(b1));
}
__device__ __forceinline__ unsigned int fasu(float x) { return __float_as_uint(x); }

// ldmatrix x4: loads 4 8x8 b32-viewed tiles; lane L of matrix i gets
// element (row L/4, b32col L%4). Address from lanes [8i, 8i+8).
#define LDSM4(d0, d1, d2, d3, saddr) \
    asm volatile("ldmatrix.sync.aligned.m8n8.x4.shared.b16 {%0,%1,%2,%3}, [%4];" \
                 : "=r"(d0), "=r"(d1), "=r"(d2), "=r"(d3) : "r"(saddr))

// ---------------- pack wq|wk|wv into [D, 3D] --------------------------------
__global__ void pack_qkv(const float* __restrict__ wq, const float* __restrict__ wk,
                         const float* __restrict__ wv, float* __restrict__ out) {
    int idx = blockIdx.x * 256 + threadIdx.x;      // float4 index
    int r = idx / (QKVW/4), c4 = idx % (QKVW/4);
    int cc = c4 * 4;
    const float* s;
    if (cc < DD)            s = wq + (size_t)r*DD + cc;
    else if (cc < 2*DD)     s = wk + (size_t)r*DD + cc - DD;
    else                    s = wv + (size_t)r*DD + cc - 2*DD;
    *(float4*)(out + (size_t)r*QKVW + cc) = *(const float4*)s;
}

// ---------------- LayerNorm -------------------------------------------------
__global__ void ln_kernel(const float* __restrict__ x, const float* __restrict__ g,
                          const float* __restrict__ b, float* __restrict__ out) {
    int row = blockIdx.x;
    int tid = threadIdx.x;                       // 256 threads
    const float4* xr = (const float4*)(x + (size_t)row * DD);
    float4 v = xr[tid];
    float s  = v.x + v.y + v.z + v.w;
    float s2 = v.x*v.x + v.y*v.y + v.z*v.z + v.w*v.w;
    #pragma unroll
    for (int o = 16; o > 0; o >>= 1) {
        s  += __shfl_down_sync(0xffffffffu, s,  o);
        s2 += __shfl_down_sync(0xffffffffu, s2, o);
    }
    __shared__ float sa[8], sb[8];
    int w = tid >> 5, l = tid & 31;
    if (l == 0) { sa[w] = s; sb[w] = s2; }
    __syncthreads();
    if (w == 0) {
        s  = (l < 8) ? sa[l] : 0.f;
        s2 = (l < 8) ? sb[l] : 0.f;
        #pragma unroll
        for (int o = 4; o > 0; o >>= 1) {
            s  += __shfl_down_sync(0xffffffffu, s,  o);
            s2 += __shfl_down_sync(0xffffffffu, s2, o);
        }
        if (l == 0) { sa[0] = s; sb[0] = s2; }
    }
    __syncthreads();
    float mean = sa[0] * (1.0f / DD);
    float var  = sb[0] * (1.0f / DD) - mean * mean;
    float inv  = rsqrtf(var + EPS);
    float4 gg = ((const float4*)g)[tid];
    float4 bb = ((const float4*)b)[tid];
    float4 o4;
    o4.x = (v.x - mean) * inv * gg.x + bb.x;
    o4.y = (v.y - mean) * inv * gg.y + bb.y;
    o4.z = (v.z - mean) * inv * gg.z + bb.z;
    o4.w = (v.w - mean) * inv * gg.w + bb.w;
    ((float4*)(out + (size_t)row * DD))[tid] = o4;
}

// ---------------- TF32 tensor-core GEMM (128x256 tile, warp 64x64) ---------
#define AS_STR 36
#define BS_STR 264
#define AS_SZ (128*AS_STR)
#define BS_SZ (32*BS_STR)
#define G2_SMEM ((2*AS_SZ + 2*BS_SZ)*4)

template<int EPI>  // 0=none, 1=relu(C+bias), 2=C+res, 3=C+bias+res
__global__ void __launch_bounds__(256, 1)
tgemm2(const float* __restrict__ A, const float* __restrict__ B,
       const float* __restrict__ bias, const float* __restrict__ res,
       float* __restrict__ C, int M, int N, int K) {
    extern __shared__ float smx[];
    float* As0 = smx;
    float* As1 = smx + AS_SZ;
    float* Bs0 = smx + 2*AS_SZ;
    float* Bs1 = smx + 2*AS_SZ + BS_SZ;
    unsigned int smem_u = (unsigned int)__cvta_generic_to_shared(smx);

    int tid = threadIdx.x, lane = tid & 31, warp = tid >> 5;
    int g = lane >> 2, qd = lane & 3;
    int wm = warp >> 2, wn = warp & 3;             // warp grid 2x4
    int rowBase = blockIdx.y * 128, colBase = blockIdx.x * 256;

    // ldmatrix per-lane A-fragment address offset (bytes, within As buffer):
    // matrices: m0=(r+0,c+0) m1=(r+8,c+0) m2=(r+0,c+4) m3=(r+8,c+4)
    int lmrow = (lane & 7) + ((lane >> 3) & 1) * 8;
    int lmcol = ((lane >> 4) & 1) * 4;
    unsigned int a_frag_off = (unsigned)((wm*64 + lmrow) * AS_STR + lmcol) * 4u;

    float acc[4][8][4];
    #pragma unroll
    for (int mt = 0; mt < 4; mt++)
        #pragma unroll
        for (int nt = 0; nt < 8; nt++)
            #pragma unroll
            for (int e = 0; e < 4; e++) acc[mt][nt][e] = 0.f;

    #define LOAD_A(dst, k0)                                                     \
        { _Pragma("unroll")                                                     \
          for (int i = 0; i < 4; i++) {                                         \
              int ch = tid + 256*i;                                             \
              int r = ch >> 3, kc = (ch & 7) * 4;                               \
              unsigned int s = (unsigned int)__cvta_generic_to_shared(&(dst)[r*AS_STR + kc]); \
              cp_async16(s, A + (size_t)(rowBase + r) * K + (k0) + kc);         \
          } }
    #define LOAD_B(dst, k0)                                                     \
        { _Pragma("unroll")                                                     \
          for (int i = 0; i < 8; i++) {                                         \
              int ch = tid + 256*i;                                             \
              int r = ch >> 6, nc = (ch & 63) * 4;                              \
              unsigned int s = (unsigned int)__cvta_generic_to_shared(&(dst)[r*BS_STR + nc]); \
              cp_async16(s, B + (size_t)((k0) + r) * N + colBase + nc);         \
          } }

    LOAD_A(As0, 0); LOAD_B(Bs0, 0); cp_commit();
    int nk = K >> 5;
    for (int kt = 0; kt < nk; kt++) {
        cp_wait0();
        __syncthreads();    // stage kt fully visible; all warps done with buf[kt^1]
        const float* b_s = (kt & 1) ? Bs1 : Bs0;
        unsigned int a_su = smem_u + ((kt & 1) ? AS_SZ*4u : 0u);
        if (kt + 1 < nk) {
            float* an = (kt & 1) ? As0 : As1;
            float* bn = (kt & 1) ? Bs0 : Bs1;
            LOAD_A(an, (kt + 1) * 32); LOAD_B(bn, (kt + 1) * 32); cp_commit();
        }
        #pragma unroll
        for (int ks = 0; ks < 4; ks++) {
            unsigned int af[4][4], bf[8][2];
            int c0 = ks*8 + qd;
            #pragma unroll
            for (int mt = 0; mt < 4; mt++) {
                LDSM4(af[mt][0], af[mt][1], af[mt][2], af[mt][3],
                      a_su + a_frag_off + (unsigned)(mt*16*AS_STR*4 + ks*32));
            }
            #pragma unroll
            for (int nt = 0; nt < 8; nt++) {
                int nn = wn*64 + nt*8 + g;
                bf[nt][0] = fasu(b_s[ c0   *BS_STR + nn]);
                bf[nt][1] = fasu(b_s[(c0+4)*BS_STR + nn]);
            }
            #pragma unroll
            for (int mt = 0; mt < 4; mt++)
                #pragma unroll
                for (int nt = 0; nt < 8; nt++)
                    mma_tf32(acc[mt][nt][0], acc[mt][nt][1], acc[mt][nt][2], acc[mt][nt][3],
                             af[mt][0], af[mt][1], af[mt][2], af[mt][3],
                             bf[nt][0], bf[nt][1]);
        }
        // no bottom barrier: top-of-next-iter sync gates buffer overwrite
    }

    #pragma unroll
    for (int mt = 0; mt < 4; mt++) {
        int r = rowBase + wm*64 + mt*16 + g;
        #pragma unroll
        for (int nt = 0; nt < 8; nt++) {
            int c = colBase + wn*64 + nt*8 + qd*2;
            float v00 = acc[mt][nt][0], v01 = acc[mt][nt][1];
            float v10 = acc[mt][nt][2], v11 = acc[mt][nt][3];
            if (EPI == 1 || EPI == 3) {
                float b0 = bias[c], b1 = bias[c+1];
                v00 += b0; v01 += b1; v10 += b0; v11 += b1;
            }
            if (EPI == 1) {
                v00 = fmaxf(v00, 0.f); v01 = fmaxf(v01, 0.f);
                v10 = fmaxf(v10, 0.f); v11 = fmaxf(v11, 0.f);
            }
            if (EPI >= 2) {
                float2 r0 = *(const float2*)(res + (size_t)r    *N + c);
                float2 r1 = *(const float2*)(res + (size_t)(r+8)*N + c);
                v00 += r0.x; v01 += r0.y; v10 += r1.x; v11 += r1.y;
            }
            float2 o0; o0.x = v00; o0.y = v01;
            float2 o1; o1.x = v10; o1.y = v11;
            *(float2*)(C + (size_t)r    *N + c) = o0;
            *(float2*)(C + (size_t)(r+8)*N + c) = o1;
        }
    }
    #undef LOAD_A
    #undef LOAD_B
}

// ---------------- Flash attention v3: BM=128, ldmatrix K/P -----------------
#define FP 68
#define FA_SMEM ((128*FP + 4*64*FP)*4)     // 104448 bytes -> 2 CTAs/SM
__global__ void __launch_bounds__(256, 2)
fa_tc(const float* __restrict__ QKV, float* __restrict__ O) {
    extern __shared__ float smx[];
    float* QsPs = smx;                    // 128*FP: Q staging, then P
    float* Ks0  = smx  + 128*FP;
    float* Ks1  = Ks0  + 64*FP;
    float* Vs0  = Ks1  + 64*FP;
    float* Vs1  = Vs0  + 64*FP;
    unsigned int smem_u = (unsigned int)__cvta_generic_to_shared(smx);
    unsigned int Ks0_u = smem_u + 128*FP*4;
    unsigned int Ks1_u = Ks0_u + 64*FP*4;

    int tid = threadIdx.x, lane = tid & 31, warp = tid >> 5;   // 8 warps
    int g = lane >> 2, qd = lane & 3;
    int qt = blockIdx.x, bh = blockIdx.y;
    int b = bh >> 4, h = bh & 15;
    size_t base = (size_t)b * SS * QKVW + (size_t)h * DKK;
    const float* Qp = QKV + base;
    const float* Kp = QKV + base + DD;
    const float* Vp = QKV + base + 2*DD;

    // ldmatrix per-lane offsets
    // K (B-frag order b0,b1,b0',b1'): m1 -> col+4, m2/m3 -> row+8
    int krow = (lane & 7) + ((lane >> 4) & 1) * 8;
    int kcol = ((lane >> 3) & 1) * 4;
    unsigned int k_frag_off = (unsigned)(krow*FP + kcol) * 4u;
    // P (A-frag order a0,a1,a2,a3): m1/m3 -> row+8, m2/m3 -> col+4
    int prow = warp*16 + (lane & 7) + ((lane >> 3) & 1) * 8;
    int pcol = ((lane >> 4) & 1) * 4;
    unsigned int p_frag_off = (unsigned)(prow*FP + pcol) * 4u;

    #define LOAD_KV(kb, vb, kt)                                                  \
        for (int c = tid; c < 64*16; c += 256) {                                 \
            int r = c >> 4, cc = (c & 15) * 4;                                   \
            size_t go = (size_t)((kt)*64 + r)*QKVW + cc;                         \
            cp_async16((unsigned int)__cvta_generic_to_shared(&(kb)[r*FP + cc]), Kp + go); \
            cp_async16((unsigned int)__cvta_generic_to_shared(&(vb)[r*FP + cc]), Vp + go); \
        }                                                                        \
        cp_commit();

    // kick off first KV load, then stage Q (128 rows)
    LOAD_KV(Ks0, Vs0, 0);
    for (int c = tid; c < 128*16; c += 256) {
        int r = c >> 4, cc = (c & 15) * 4;
        float4 q4 = *(const float4*)(Qp + (size_t)(qt*128 + r)*QKVW + cc);
        QsPs[r*FP + cc + 0] = q4.x * 0.125f;
        QsPs[r*FP + cc + 1] = q4.y * 0.125f;
        QsPs[r*FP + cc + 2] = q4.z * 0.125f;
        QsPs[r*FP + cc + 3] = q4.w * 0.125f;
    }
    __syncthreads();

    int r0 = warp*16 + g;     // this warp's rows r0, r0+8
    // extract Q fragments via ldmatrix (same A-frag mapping as P)
    unsigned int qf[8][4];
    #pragma unroll
    for (int ks = 0; ks < 8; ks++) {
        LDSM4(qf[ks][0], qf[ks][1], qf[ks][2], qf[ks][3],
              smem_u + p_frag_off + (unsigned)(ks*32));
    }
    float* Ps = QsPs;         // alias: Q staging buffer becomes P

    float m0 = -1e30f, m1 = -1e30f, l0 = 0.f, l1 = 0.f;
    float o[8][4];
    #pragma unroll
    for (int nt = 0; nt < 8; nt++)
        #pragma unroll
        for (int e = 0; e < 4; e++) o[nt][e] = 0.f;

    const int NT = SS/64;
    for (int kt = 0; kt < NT; kt++) {
        cp_wait0();
        __syncthreads();   // tile kt visible; all warps done with buf[kt^1]
        float* Vsb = (kt & 1) ? Vs1 : Vs0;
        unsigned int ks_u = (kt & 1) ? Ks1_u : Ks0_u;
        if (kt + 1 < NT) {
            float* kn = (kt & 1) ? Ks0 : Ks1;
            float* vn = (kt & 1) ? Vs0 : Vs1;
            LOAD_KV(kn, vn, kt + 1);
        }

        // S = Q @ K^T  (K fragments via ldmatrix: 2 nt per LDSM.x4)
        float sc[8][4];
        #pragma unroll
        for (int nt = 0; nt < 8; nt++)
            #pragma unroll
            for (int e = 0; e < 4; e++) sc[nt][e] = 0.f;
        #pragma unroll
        for (int ks = 0; ks < 8; ks++) {
            #pragma unroll
            for (int ntp = 0; ntp < 4; ntp++) {
                unsigned int kb0, kb1, kb2, kb3;
                LDSM4(kb0, kb1, kb2, kb3,
                      ks_u + k_frag_off + (unsigned)(ntp*16*FP*4 + ks*32));
                mma_tf32(sc[2*ntp  ][0], sc[2*ntp  ][1], sc[2*ntp  ][2], sc[2*ntp  ][3],
                         qf[ks][0], qf[ks][1], qf[ks][2], qf[ks][3], kb0, kb1);
                mma_tf32(sc[2*ntp+1][0], sc[2*ntp+1][1], sc[2*ntp+1][2], sc[2*ntp+1][3],
                         qf[ks][0], qf[ks][1], qf[ks][2], qf[ks][3], kb2, kb3);
            }
        }

        // online softmax (rows r0, r0+8)
        float mx0 = -1e30f, mx1 = -1e30f;
        #pragma unroll
        for (int nt = 0; nt < 8; nt++) {
            mx0 = fmaxf(mx0, fmaxf(sc[nt][0], sc[nt][1]));
            mx1 = fmaxf(mx1, fmaxf(sc[nt][2], sc[nt][3]));
        }
        mx0 = fmaxf(mx0, __shfl_xor_sync(0xffffffffu, mx0, 1));
        mx0 = fmaxf(mx0, __shfl_xor_sync(0xffffffffu, mx0, 2));
        mx1 = fmaxf(mx1, __shfl_xor_sync(0xffffffffu, mx1, 1));
        mx1 = fmaxf(mx1, __shfl_xor_sync(0xffffffffu, mx1, 2));
        float nm0 = fmaxf(m0, mx0), nm1 = fmaxf(m1, mx1);
        float sum0 = 0.f, sum1 = 0.f;
        #pragma unroll
        for (int nt = 0; nt < 8; nt++) {
            sc[nt][0] = __expf(sc[nt][0] - nm0);
            sc[nt][1] = __expf(sc[nt][1] - nm0);
            sc[nt][2] = __expf(sc[nt][2] - nm1);
            sc[nt][3] = __expf(sc[nt][3] - nm1);
            sum0 += sc[nt][0] + sc[nt][1];
            sum1 += sc[nt][2] + sc[nt][3];
        }
        sum0 += __shfl_xor_sync(0xffffffffu, sum0, 1);
        sum0 += __shfl_xor_sync(0xffffffffu, sum0, 2);
        sum1 += __shfl_xor_sync(0xffffffffu, sum1, 1);
        sum1 += __shfl_xor_sync(0xffffffffu, sum1, 2);
        float al0 = __expf(m0 - nm0), al1 = __expf(m1 - nm1);
        m0 = nm0; m1 = nm1;
        l0 = l0 * al0 + sum0;
        l1 = l1 * al1 + sum1;
        #pragma unroll
        for (int nt = 0; nt < 8; nt++) {
            o[nt][0] *= al0; o[nt][1] *= al0;
            o[nt][2] *= al1; o[nt][3] *= al1;
        }
        // stash P (warp-private rows) — warp-level sync only
        #pragma unroll
        for (int nt = 0; nt < 8; nt++) {
            float2 p0; p0.x = sc[nt][0]; p0.y = sc[nt][1];
            float2 p1; p1.x = sc[nt][2]; p1.y = sc[nt][3];
            *(float2*)&Ps[ r0   *FP + nt*8 + qd*2] = p0;
            *(float2*)&Ps[(r0+8)*FP + nt*8 + qd*2] = p1;
        }
        __syncwarp();

        // O += P @ V  (P fragments via ldmatrix; V scalar)
        #pragma unroll
        for (int ks = 0; ks < 8; ks++) {
            unsigned int a0, a1, a2, a3;
            LDSM4(a0, a1, a2, a3, smem_u + p_frag_off + (unsigned)(ks*32));
            #pragma unroll
            for (int nt = 0; nt < 8; nt++) {
                unsigned int b0 = fasu(Vsb[(ks*8 + qd  )*FP + nt*8 + g]);
                unsigned int b1 = fasu(Vsb[(ks*8 + qd+4)*FP + nt*8 + g]);
                mma_tf32(o[nt][0], o[nt][1], o[nt][2], o[nt][3],
                         a0, a1, a2, a3, b0, b1);
            }
        }
        // no bottom barrier: next iteration's top sync gates buffer overwrite
    }
    #undef LOAD_KV

    float inv0 = 1.f / l0, inv1 = 1.f / l1;
    size_t srow0 = (size_t)(b*SS + qt*128 + r0);
    #pragma unroll
    for (int nt = 0; nt < 8; nt++) {
        int c = h*DKK + nt*8 + qd*2;
        float2 o0; o0.x = o[nt][0]*inv0; o0.y = o[nt][1]*inv0;
        float2 o1; o1.x = o[nt][2]*inv1; o1.y = o[nt][3]*inv1;
        *(float2*)(O +  srow0     *DD + c) = o0;
        *(float2*)(O + (srow0 + 8)*DD + c) = o1;
    }
}

// ---------------- launch ----------------------------------------------------
extern "C" void kernel_launch(void* const* d_in, const int* in_sizes, int n_in,
                              void* d_out, int out_size) {
    (void)in_sizes; (void)n_in; (void)out_size;
    const float* x   = (const float*)d_in[0];
    const float* wq  = (const float*)d_in[1];
    const float* wk  = (const float*)d_in[2];
    const float* wv  = (const float*)d_in[3];
    const float* wo  = (const float*)d_in[4];
    const float* w1  = (const float*)d_in[5];
    const float* b1  = (const float*)d_in[6];
    const float* w2  = (const float*)d_in[7];
    const float* b2  = (const float*)d_in[8];
    const float* g1  = (const float*)d_in[9];
    const float* be1 = (const float*)d_in[10];
    const float* g2  = (const float*)d_in[11];
    const float* be2 = (const float*)d_in[12];
    float* out = (float*)d_out;

    float *h, *qkv, *attn, *x1, *h2, *ffn, *wqkv;
    cudaGetSymbolAddress((void**)&h,    g_h);
    cudaGetSymbolAddress((void**)&qkv,  g_qkv);
    cudaGetSymbolAddress((void**)&attn, g_attn);
    cudaGetSymbolAddress((void**)&x1,   g_x1);
    cudaGetSymbolAddress((void**)&h2,   g_h2);
    cudaGetSymbolAddress((void**)&ffn,  g_ffn);
    cudaGetSymbolAddress((void**)&wqkv, g_wqkv);

    cudaFuncSetAttribute(tgemm2<0>, cudaFuncAttributeMaxDynamicSharedMemorySize, G2_SMEM);
    cudaFuncSetAttribute(tgemm2<1>, cudaFuncAttributeMaxDynamicSharedMemorySize, G2_SMEM);
    cudaFuncSetAttribute(tgemm2<2>, cudaFuncAttributeMaxDynamicSharedMemorySize, G2_SMEM);
    cudaFuncSetAttribute(tgemm2<3>, cudaFuncAttributeMaxDynamicSharedMemorySize, G2_SMEM);
    cudaFuncSetAttribute(fa_tc,     cudaFuncAttributeMaxDynamicSharedMemorySize, FA_SMEM);

    // 0) pack weights
    pack_qkv<<<(DD*QKVW/4)/256, 256>>>(wq, wk, wv, wqkv);
    // 1) LN1
    ln_kernel<<<NTOK, 256>>>(x, g1, be1, h);
    // 2) fused QKV projection
    tgemm2<0><<<dim3(QKVW/256, NTOK/128), 256, G2_SMEM>>>(h, wqkv, nullptr, nullptr, qkv, NTOK, QKVW, DD);
    // 3) attention (BM=128)
    fa_tc<<<dim3(SS/128, BBATCH*HH), 256, FA_SMEM>>>(qkv, attn);
    // 4) x1 = x + attn @ wo
    tgemm2<2><<<dim3(DD/256, NTOK/128), 256, G2_SMEM>>>(attn, wo, nullptr, x, x1, NTOK, DD, DD);
    // 5) LN2
    ln_kernel<<<NTOK, 256>>>(x1, g2, be2, h2);
    // 6) ffn = relu(h2 @ w1 + b1)
    tgemm2<1><<<dim3(DFFN/256, NTOK/128), 256, G2_SMEM>>>(h2, w1, b1, nullptr, ffn, NTOK, DFFN, DD);
    // 7) out = x1 + ffn @ w2 + b2
    tgemm2<3><<<dim3(DD/256, NTOK/128), 256, G2_SMEM>>>(ffn, w2, b2, x1, out, NTOK, DD, DFFN);
}